// round 11
// baseline (speedup 1.0000x reference)
#include <cuda_runtime.h>
#include <cuda_bf16.h>
#include <math.h>
#include <stdint.h>

#define S_LEN 2048
#define DIM 2048
#define NH 32
#define NKV 8
#define HD 64
#define KVDIM (NKV * HD)   // 512

// ---------------------------------------------------------------------------
// Scratch (bf16 hi/lo pairs stored as uint16)
// ---------------------------------------------------------------------------
__device__ __align__(16) uint16_t g_xh[S_LEN * DIM],  g_xl[S_LEN * DIM];
__device__ __align__(16) uint16_t g_wqh[DIM * DIM],   g_wql[DIM * DIM];
__device__ __align__(16) uint16_t g_wkh[KVDIM * DIM], g_wkl[KVDIM * DIM];
__device__ __align__(16) uint16_t g_wvh[KVDIM * DIM], g_wvl[KVDIM * DIM];
__device__ __align__(16) uint16_t g_woh[DIM * DIM],   g_wol[DIM * DIM];
__device__ __align__(16) uint16_t g_qh[S_LEN * DIM],  g_ql[S_LEN * DIM];
__device__ __align__(16) uint16_t g_kh[S_LEN * KVDIM], g_kl[S_LEN * KVDIM];
__device__ __align__(16) uint16_t g_vh[S_LEN * KVDIM], g_vl[S_LEN * KVDIM];
__device__ __align__(16) uint16_t g_aoh[S_LEN * DIM], g_aol[S_LEN * DIM];
__device__ float g_ct[S_LEN * 32];
__device__ float g_st[S_LEN * 32];

// ---------------------------------------------------------------------------
// helpers
// ---------------------------------------------------------------------------
__device__ __forceinline__ uint32_t smem_u32(const void* p) {
    uint32_t a;
    asm("{ .reg .u64 t; cvta.to.shared.u64 t, %1; cvt.u32.u64 %0, t; }"
        : "=r"(a) : "l"(p));
    return a;
}
__device__ __forceinline__ void ldm_x4(uint32_t* r, uint32_t addr) {
    asm volatile("ldmatrix.sync.aligned.m8n8.x4.shared.b16 {%0,%1,%2,%3}, [%4];"
                 : "=r"(r[0]), "=r"(r[1]), "=r"(r[2]), "=r"(r[3]) : "r"(addr));
}
__device__ __forceinline__ void ldm_x4_t(uint32_t* r, uint32_t addr) {
    asm volatile("ldmatrix.sync.aligned.m8n8.x4.trans.shared.b16 {%0,%1,%2,%3}, [%4];"
                 : "=r"(r[0]), "=r"(r[1]), "=r"(r[2]), "=r"(r[3]) : "r"(addr));
}
__device__ __forceinline__ void mma_bf16(float* d, const uint32_t* a,
                                         const uint32_t* b) {
    asm volatile(
        "mma.sync.aligned.m16n8k16.row.col.f32.bf16.bf16.f32 "
        "{%0,%1,%2,%3}, {%4,%5,%6,%7}, {%8,%9}, {%0,%1,%2,%3};"
        : "+f"(d[0]), "+f"(d[1]), "+f"(d[2]), "+f"(d[3])
        : "r"(a[0]), "r"(a[1]), "r"(a[2]), "r"(a[3]), "r"(b[0]), "r"(b[1]));
}
__device__ __forceinline__ void split2(float x, float y, uint32_t& hi, uint32_t& lo) {
    __nv_bfloat162 h = __float22bfloat162_rn(make_float2(x, y));
    hi = *reinterpret_cast<uint32_t*>(&h);
    __nv_bfloat162 l = __float22bfloat162_rn(make_float2(
        x - __bfloat162float(h.x), y - __bfloat162float(h.y)));
    lo = *reinterpret_cast<uint32_t*>(&l);
}

#define CP_ASYNC16(dst_u32, gsrc) \
    asm volatile("cp.async.cg.shared.global [%0], [%1], 16;" \
                 :: "r"(dst_u32), "l"(gsrc) : "memory")
#define CP_COMMIT() asm volatile("cp.async.commit_group;" ::: "memory")
#define CP_WAIT(n)  asm volatile("cp.async.wait_group %0;" :: "n"(n) : "memory")

// ---------------------------------------------------------------------------
// Fused fp32 -> bf16 hi/lo split for all five inputs (one launch)
// ---------------------------------------------------------------------------
#define N4_X  (S_LEN * DIM / 4)
#define N4_WQ (DIM * DIM / 4)
#define N4_WK (KVDIM * DIM / 4)
#define N4_WV (KVDIM * DIM / 4)
#define N4_WO (DIM * DIM / 4)
#define C1 (N4_X)
#define C2 (C1 + N4_WQ)
#define C3 (C2 + N4_WK)
#define C4 (C3 + N4_WV)
#define C5 (C4 + N4_WO)

__global__ __launch_bounds__(256)
void conv_split_all(const float4* __restrict__ x, const float4* __restrict__ wq,
                    const float4* __restrict__ wk, const float4* __restrict__ wv,
                    const float4* __restrict__ wo) {
    int i = blockIdx.x * 256 + threadIdx.x;
    if (i >= C5) return;
    const float4* src;
    uint2 *dh, *dl;
    int j;
    if (i < C1)      { src = x;  dh = (uint2*)g_xh;  dl = (uint2*)g_xl;  j = i; }
    else if (i < C2) { src = wq; dh = (uint2*)g_wqh; dl = (uint2*)g_wql; j = i - C1; }
    else if (i < C3) { src = wk; dh = (uint2*)g_wkh; dl = (uint2*)g_wkl; j = i - C2; }
    else if (i < C4) { src = wv; dh = (uint2*)g_wvh; dl = (uint2*)g_wvl; j = i - C3; }
    else             { src = wo; dh = (uint2*)g_woh; dl = (uint2*)g_wol; j = i - C4; }
    float4 f = src[j];
    uint2 h, l;
    split2(f.x, f.y, h.x, l.x);
    split2(f.z, f.w, h.y, l.y);
    dh[j] = h;
    dl[j] = l;
}

// ---------------------------------------------------------------------------
// RoPE cos/sin table (verified: fp32 angle, high-precision trig)
// ---------------------------------------------------------------------------
__global__ void rope_table_kernel() {
    int s = blockIdx.x;
    int i = threadIdx.x;
    float e = (float)i / 32.0f;
    float fr = 1.0f / powf(10000.0f, e);
    float angf = (float)s * fr;
    double ang = (double)angf;
    g_ct[s * 32 + i] = (float)cos(ang);
    g_st[s * 32 + i] = (float)sin(ang);
}

// ---------------------------------------------------------------------------
// GEMM core pieces (3-stage cp.async ring)
// smem layout: stage s (0..2) at s*4*GSZ, arrays Ah,Al,Bh,Bl within stage.
// ---------------------------------------------------------------------------
#define GPAD 40
#define GSZ (128 * GPAD)
#define GEMM_SMEM (12 * GSZ * 2)   // 122880 bytes

__device__ __forceinline__ void gemm_load_chunk(
    uint32_t sb, int stage, int tid, int m0, int bn0, int k0,
    const uint16_t* Ah, const uint16_t* Al,
    const uint16_t* Bh, const uint16_t* Bl, int K) {
    const uint32_t st = sb + (uint32_t)stage * 4 * GSZ * 2;
#pragma unroll
    for (int i = 0; i < 2; i++) {
        int cid = tid + i * 256;
        int r = cid >> 2;
        int c = (cid & 3) * 8;
        uint32_t soff = (uint32_t)(r * GPAD + c) * 2;
        CP_ASYNC16(st + 0 * GSZ * 2 + soff, Ah + (size_t)(m0 + r) * K + k0 + c);
        CP_ASYNC16(st + 1 * GSZ * 2 + soff, Al + (size_t)(m0 + r) * K + k0 + c);
        CP_ASYNC16(st + 2 * GSZ * 2 + soff, Bh + (size_t)(bn0 + r) * K + k0 + c);
        CP_ASYNC16(st + 3 * GSZ * 2 + soff, Bl + (size_t)(bn0 + r) * K + k0 + c);
    }
}

__device__ __forceinline__ void gemm_compute_chunk(
    uint32_t sb, int stage, float acc[2][8][4],
    int wm, int wn, int a_r, int a_c, int b_r, int b_c) {
    const uint32_t st = sb + (uint32_t)stage * 4 * GSZ * 2;
    const uint32_t bAh = st, bAl = st + GSZ * 2;
    const uint32_t bBh = st + 2 * GSZ * 2, bBl = st + 3 * GSZ * 2;
#pragma unroll
    for (int ks = 0; ks < 2; ks++) {
        const int kc = ks * 16;
        uint32_t ah[2][4], al[2][4];
#pragma unroll
        for (int mi = 0; mi < 2; mi++) {
            uint32_t off = (uint32_t)((wm + mi * 16 + a_r) * GPAD + kc + a_c) * 2;
            ldm_x4(ah[mi], bAh + off);
            ldm_x4(al[mi], bAl + off);
        }
        uint32_t bh[8][2], bl[8][2];
#pragma unroll
        for (int nj = 0; nj < 4; nj++) {
            uint32_t off = (uint32_t)((wn + nj * 16 + b_r) * GPAD + kc + b_c) * 2;
            uint32_t t[4];
            ldm_x4(t, bBh + off);
            bh[nj * 2][0] = t[0]; bh[nj * 2][1] = t[1];
            bh[nj * 2 + 1][0] = t[2]; bh[nj * 2 + 1][1] = t[3];
            ldm_x4(t, bBl + off);
            bl[nj * 2][0] = t[0]; bl[nj * 2][1] = t[1];
            bl[nj * 2 + 1][0] = t[2]; bl[nj * 2 + 1][1] = t[3];
        }
#pragma unroll
        for (int mi = 0; mi < 2; mi++)
#pragma unroll
            for (int ni = 0; ni < 8; ni++) {
                mma_bf16(acc[mi][ni], ah[mi], bh[ni]);
                mma_bf16(acc[mi][ni], ah[mi], bl[ni]);
                mma_bf16(acc[mi][ni], al[mi], bh[ni]);
            }
    }
}

// ---------------------------------------------------------------------------
// Fused QKV GEMM + RoPE/scale/split epilogue. Grid (24, 16).
// ---------------------------------------------------------------------------
__global__ __launch_bounds__(256)
void qkv_gemm() {
    extern __shared__ uint16_t dsm[];
    const uint32_t sb = smem_u32(dsm);

    const int tid  = threadIdx.x;
    const int wid  = tid >> 5;
    const int lane = tid & 31;
    const int wm = (wid & 3) * 32;
    const int wn = (wid >> 2) * 64;
    const int m0 = blockIdx.y * 128;
    const int n0 = blockIdx.x * 128;

    const uint16_t *Bh, *Bl;
    int bn0, seg;
    if (n0 < 2048)      { Bh = g_wqh; Bl = g_wql; bn0 = n0;        seg = 0; }
    else if (n0 < 2560) { Bh = g_wkh; Bl = g_wkl; bn0 = n0 - 2048; seg = 1; }
    else                { Bh = g_wvh; Bl = g_wvl; bn0 = n0 - 2560; seg = 2; }

    float acc[2][8][4];
#pragma unroll
    for (int i = 0; i < 2; i++)
#pragma unroll
        for (int j = 0; j < 8; j++)
#pragma unroll
            for (int e = 0; e < 4; e++) acc[i][j][e] = 0.f;

    const int a_r = lane & 15;
    const int a_c = (lane >> 4) << 3;
    const int b_r = (lane & 7) + ((lane >> 4) << 3);
    const int b_c = ((lane >> 3) & 1) << 3;

    gemm_load_chunk(sb, 0, tid, m0, bn0, 0,  g_xh, g_xl, Bh, Bl, DIM);
    CP_COMMIT();
    gemm_load_chunk(sb, 1, tid, m0, bn0, 32, g_xh, g_xl, Bh, Bl, DIM);
    CP_COMMIT();

    for (int ck = 0; ck < 64; ck++) {
        const int cur = ck % 3;
        if (ck + 2 < 64) CP_WAIT(1); else CP_WAIT(0);
        __syncthreads();
        if (ck + 2 < 64) {
            gemm_load_chunk(sb, (ck + 2) % 3, tid, m0, bn0, (ck + 2) * 32,
                            g_xh, g_xl, Bh, Bl, DIM);
            CP_COMMIT();
        }
        gemm_compute_chunk(sb, cur, acc, wm, wn, a_r, a_c, b_r, b_c);
    }

    // ---- epilogue ----
    const int g2 = lane >> 2, t2 = lane & 3;
    if (seg < 2) {
        const int W = (seg == 0) ? DIM : KVDIM;
        uint16_t* dsth = (seg == 0) ? g_qh : g_kh;
        uint16_t* dstl = (seg == 0) ? g_ql : g_kl;
        const float scale = (seg == 0) ? 0.125f : 1.0f;
        const int cb = bn0 + wn;
#pragma unroll
        for (int mi = 0; mi < 2; mi++) {
            int r0 = m0 + wm + mi * 16 + g2;
#pragma unroll
            for (int ni = 0; ni < 4; ni++) {
                int jj = ni * 8 + 2 * t2;
                float2 c0 = *reinterpret_cast<const float2*>(g_ct + r0 * 32 + jj);
                float2 s0 = *reinterpret_cast<const float2*>(g_st + r0 * 32 + jj);
                float2 c1 = *reinterpret_cast<const float2*>(g_ct + (r0 + 8) * 32 + jj);
                float2 s1 = *reinterpret_cast<const float2*>(g_st + (r0 + 8) * 32 + jj);
                uint32_t h, l;
                float x1a = acc[mi][ni][0],     x1b = acc[mi][ni][1];
                float x2a = acc[mi][ni + 4][0], x2b = acc[mi][ni + 4][1];
                split2((x1a * c0.x - x2a * s0.x) * scale,
                       (x1b * c0.y - x2b * s0.y) * scale, h, l);
                *reinterpret_cast<uint32_t*>(dsth + (size_t)r0 * W + cb + jj) = h;
                *reinterpret_cast<uint32_t*>(dstl + (size_t)r0 * W + cb + jj) = l;
                split2((x2a * c0.x + x1a * s0.x) * scale,
                       (x2b * c0.y + x1b * s0.y) * scale, h, l);
                *reinterpret_cast<uint32_t*>(dsth + (size_t)r0 * W + cb + jj + 32) = h;
                *reinterpret_cast<uint32_t*>(dstl + (size_t)r0 * W + cb + jj + 32) = l;
                x1a = acc[mi][ni][2];     x1b = acc[mi][ni][3];
                x2a = acc[mi][ni + 4][2]; x2b = acc[mi][ni + 4][3];
                split2((x1a * c1.x - x2a * s1.x) * scale,
                       (x1b * c1.y - x2b * s1.y) * scale, h, l);
                *reinterpret_cast<uint32_t*>(dsth + (size_t)(r0 + 8) * W + cb + jj) = h;
                *reinterpret_cast<uint32_t*>(dstl + (size_t)(r0 + 8) * W + cb + jj) = l;
                split2((x2a * c1.x + x1a * s1.x) * scale,
                       (x2b * c1.y + x1b * s1.y) * scale, h, l);
                *reinterpret_cast<uint32_t*>(dsth + (size_t)(r0 + 8) * W + cb + jj + 32) = h;
                *reinterpret_cast<uint32_t*>(dstl + (size_t)(r0 + 8) * W + cb + jj + 32) = l;
            }
        }
    } else {
        const int cb = bn0 + wn;
#pragma unroll
        for (int mi = 0; mi < 2; mi++) {
            int r0 = m0 + wm + mi * 16 + g2;
#pragma unroll
            for (int ni = 0; ni < 8; ni++) {
                int cc = cb + ni * 8 + 2 * t2;
                uint32_t h, l;
                split2(acc[mi][ni][0], acc[mi][ni][1], h, l);
                *reinterpret_cast<uint32_t*>(g_vh + (size_t)r0 * KVDIM + cc) = h;
                *reinterpret_cast<uint32_t*>(g_vl + (size_t)r0 * KVDIM + cc) = l;
                split2(acc[mi][ni][2], acc[mi][ni][3], h, l);
                *reinterpret_cast<uint32_t*>(g_vh + (size_t)(r0 + 8) * KVDIM + cc) = h;
                *reinterpret_cast<uint32_t*>(g_vl + (size_t)(r0 + 8) * KVDIM + cc) = l;
            }
        }
    }
}

// ---------------------------------------------------------------------------
// O projection GEMM: out = ao @ wo^T, fp32 output.
// ---------------------------------------------------------------------------
__global__ __launch_bounds__(256)
void o_gemm(float* __restrict__ C) {
    extern __shared__ uint16_t dsm[];
    const uint32_t sb = smem_u32(dsm);

    const int tid  = threadIdx.x;
    const int wid  = tid >> 5;
    const int lane = tid & 31;
    const int wm = (wid & 3) * 32;
    const int wn = (wid >> 2) * 64;
    const int m0 = blockIdx.y * 128;
    const int n0 = blockIdx.x * 128;

    float acc[2][8][4];
#pragma unroll
    for (int i = 0; i < 2; i++)
#pragma unroll
        for (int j = 0; j < 8; j++)
#pragma unroll
            for (int e = 0; e < 4; e++) acc[i][j][e] = 0.f;

    const int a_r = lane & 15;
    const int a_c = (lane >> 4) << 3;
    const int b_r = (lane & 7) + ((lane >> 4) << 3);
    const int b_c = ((lane >> 3) & 1) << 3;

    gemm_load_chunk(sb, 0, tid, m0, n0, 0,  g_aoh, g_aol, g_woh, g_wol, DIM);
    CP_COMMIT();
    gemm_load_chunk(sb, 1, tid, m0, n0, 32, g_aoh, g_aol, g_woh, g_wol, DIM);
    CP_COMMIT();

    for (int ck = 0; ck < 64; ck++) {
        const int cur = ck % 3;
        if (ck + 2 < 64) CP_WAIT(1); else CP_WAIT(0);
        __syncthreads();
        if (ck + 2 < 64) {
            gemm_load_chunk(sb, (ck + 2) % 3, tid, m0, n0, (ck + 2) * 32,
                            g_aoh, g_aol, g_woh, g_wol, DIM);
            CP_COMMIT();
        }
        gemm_compute_chunk(sb, cur, acc, wm, wn, a_r, a_c, b_r, b_c);
    }

    const int g2 = lane >> 2, t2 = lane & 3;
#pragma unroll
    for (int mi = 0; mi < 2; mi++) {
        int r0 = m0 + wm + mi * 16 + g2;
#pragma unroll
        for (int ni = 0; ni < 8; ni++) {
            int c = n0 + wn + ni * 8 + t2 * 2;
            *reinterpret_cast<float2*>(C + (size_t)r0 * DIM + c) =
                make_float2(acc[mi][ni][0], acc[mi][ni][1]);
            *reinterpret_cast<float2*>(C + (size_t)(r0 + 8) * DIM + c) =
                make_float2(acc[mi][ni][2], acc[mi][ni][3]);
        }
    }
}

// ---------------------------------------------------------------------------
// Tensor-core flash attention with 2-stage cp.async K/V pipeline.
// Grid (32 qtiles, 32 heads), 128 threads (4 warps), 64x64 tiles.
// ---------------------------------------------------------------------------
#define KPAD 72
#define AARR (64 * KPAD * 2)      // bytes per array per stage (9216)
#define ASTG (4 * AARR)           // bytes per stage (36864)
#define ATTN_SMEM (2 * ASTG)      // 73728
#define LOG2E 1.4426950408889634f

__global__ __launch_bounds__(128)
void attn_tc_kernel() {
    extern __shared__ uint16_t asm_[];
    const uint32_t sb = smem_u32(asm_);

    const int qt = (int)gridDim.x - 1 - (int)blockIdx.x;
    const int h  = blockIdx.y;
    const int kvh = h >> 2;
    const int tid = threadIdx.x;
    const int wid = tid >> 5;
    const int lane = tid & 31;
    const int g = lane >> 2;
    const int t = lane & 3;

    // ---- stage Q into stage-0 Kh/Kl region, pull fragments ----
#pragma unroll
    for (int it = 0; it < 4; it++) {
        int cid = tid + it * 128;
        int r = cid >> 3;
        int c = (cid & 7) * 8;
        *reinterpret_cast<uint4*>(&asm_[(0 * AARR / 2) + r * KPAD + c]) =
            *reinterpret_cast<const uint4*>(
                g_qh + (size_t)(qt * 64 + r) * DIM + h * HD + c);
        *reinterpret_cast<uint4*>(&asm_[(1 * AARR / 2) + r * KPAD + c]) =
            *reinterpret_cast<const uint4*>(
                g_ql + (size_t)(qt * 64 + r) * DIM + h * HD + c);
    }
    __syncthreads();

    uint32_t qh[4][4], ql[4][4];
    {
        int row = wid * 16 + (lane & 15);
        int col = ((lane >> 4) & 1) * 8;
#pragma unroll
        for (int c = 0; c < 4; c++) {
            uint32_t off = (uint32_t)(row * KPAD + c * 16 + col) * 2;
            ldm_x4(qh[c], sb + 0 * AARR + off);
            ldm_x4(ql[c], sb + 1 * AARR + off);
        }
    }
    __syncthreads();

    float mr[2] = {-INFINITY, -INFINITY};
    float lr[2] = {0.f, 0.f};
    float D[8][4];
#pragma unroll
    for (int i = 0; i < 8; i++)
#pragma unroll
        for (int j = 0; j < 4; j++) D[i][j] = 0.f;

    const int kb_row = (lane & 7) + ((lane >> 4) << 3);
    const int kb_col = ((lane >> 3) & 1) * 8;
    const int vb_row = (lane & 7) + (((lane >> 3) & 1) << 3);
    const int vb_col = ((lane >> 4) & 1) * 8;

    // async K/V tile stage
    auto stage_kv = [&](int kt, int stage) {
        const uint32_t st = sb + (uint32_t)stage * ASTG;
#pragma unroll
        for (int it = 0; it < 4; it++) {
            int cid = tid + it * 128;
            int r = cid >> 3;
            int c = (cid & 7) * 8;
            size_t off = (size_t)(kt * 64 + r) * KVDIM + kvh * HD + c;
            uint32_t soff = (uint32_t)(r * KPAD + c) * 2;
            CP_ASYNC16(st + 0 * AARR + soff, g_kh + off);
            CP_ASYNC16(st + 1 * AARR + soff, g_kl + off);
            CP_ASYNC16(st + 2 * AARR + soff, g_vh + off);
            CP_ASYNC16(st + 3 * AARR + soff, g_vl + off);
        }
    };

    stage_kv(0, 0);
    CP_COMMIT();

    for (int kt = 0; kt <= qt; kt++) {
        const uint32_t st = sb + (uint32_t)(kt & 1) * ASTG;
        const uint32_t bKh = st, bKl = st + AARR;
        const uint32_t bVh = st + 2 * AARR, bVl = st + 3 * AARR;

        CP_WAIT(0);
        __syncthreads();
        if (kt < qt) {
            stage_kv(kt + 1, (kt + 1) & 1);
            CP_COMMIT();
        }

        float S[8][4];
#pragma unroll
        for (int i = 0; i < 8; i++)
#pragma unroll
            for (int j = 0; j < 4; j++) S[i][j] = 0.f;

#pragma unroll
        for (int c = 0; c < 4; c++) {
#pragma unroll
            for (int nbp = 0; nbp < 4; nbp++) {
                uint32_t kh[4], kl[4];
                uint32_t off = (uint32_t)((nbp * 16 + kb_row) * KPAD + c * 16 + kb_col) * 2;
                ldm_x4(kh, bKh + off);
                ldm_x4(kl, bKl + off);
                mma_bf16(S[2 * nbp],     qh[c], kh);
                mma_bf16(S[2 * nbp],     qh[c], kl);
                mma_bf16(S[2 * nbp],     ql[c], kh);
                mma_bf16(S[2 * nbp + 1], qh[c], kh + 2);
                mma_bf16(S[2 * nbp + 1], qh[c], kl + 2);
                mma_bf16(S[2 * nbp + 1], ql[c], kh + 2);
            }
        }

        if (kt == qt) {
            int r0 = wid * 16 + g;
#pragma unroll
            for (int nb = 0; nb < 8; nb++) {
                int c0 = nb * 8 + 2 * t;
                if (c0 > r0)     S[nb][0] = -INFINITY;
                if (c0 + 1 > r0) S[nb][1] = -INFINITY;
                if (c0 > r0 + 8)     S[nb][2] = -INFINITY;
                if (c0 + 1 > r0 + 8) S[nb][3] = -INFINITY;
            }
        }

        float mx0 = -INFINITY, mx1 = -INFINITY;
#pragma unroll
        for (int nb = 0; nb < 8; nb++) {
            mx0 = fmaxf(mx0, fmaxf(S[nb][0], S[nb][1]));
            mx1 = fmaxf(mx1, fmaxf(S[nb][2], S[nb][3]));
        }
        mx0 = fmaxf(mx0, __shfl_xor_sync(0xffffffffu, mx0, 1));
        mx0 = fmaxf(mx0, __shfl_xor_sync(0xffffffffu, mx0, 2));
        mx1 = fmaxf(mx1, __shfl_xor_sync(0xffffffffu, mx1, 1));
        mx1 = fmaxf(mx1, __shfl_xor_sync(0xffffffffu, mx1, 2));
        float newm0 = fmaxf(mr[0], mx0);
        float newm1 = fmaxf(mr[1], mx1);
        float a0 = exp2f((mr[0] - newm0) * LOG2E);
        float a1 = exp2f((mr[1] - newm1) * LOG2E);
        mr[0] = newm0; mr[1] = newm1;

        float sum0 = 0.f, sum1 = 0.f;
#pragma unroll
        for (int nb = 0; nb < 8; nb++) {
            S[nb][0] = exp2f((S[nb][0] - newm0) * LOG2E);
            S[nb][1] = exp2f((S[nb][1] - newm0) * LOG2E);
            S[nb][2] = exp2f((S[nb][2] - newm1) * LOG2E);
            S[nb][3] = exp2f((S[nb][3] - newm1) * LOG2E);
            sum0 += S[nb][0] + S[nb][1];
            sum1 += S[nb][2] + S[nb][3];
        }
        sum0 += __shfl_xor_sync(0xffffffffu, sum0, 1);
        sum0 += __shfl_xor_sync(0xffffffffu, sum0, 2);
        sum1 += __shfl_xor_sync(0xffffffffu, sum1, 1);
        sum1 += __shfl_xor_sync(0xffffffffu, sum1, 2);
        lr[0] = lr[0] * a0 + sum0;
        lr[1] = lr[1] * a1 + sum1;

        uint32_t ph[4][4], pl[4][4];
#pragma unroll
        for (int c = 0; c < 4; c++) {
            int nA = 2 * c, nB = 2 * c + 1;
            split2(S[nA][0], S[nA][1], ph[c][0], pl[c][0]);
            split2(S[nA][2], S[nA][3], ph[c][1], pl[c][1]);
            split2(S[nB][0], S[nB][1], ph[c][2], pl[c][2]);
            split2(S[nB][2], S[nB][3], ph[c][3], pl[c][3]);
        }

#pragma unroll
        for (int db = 0; db < 8; db++) {
            D[db][0] *= a0; D[db][1] *= a0;
            D[db][2] *= a1; D[db][3] *= a1;
        }

#pragma unroll
        for (int c = 0; c < 4; c++) {
#pragma unroll
            for (int dbp = 0; dbp < 4; dbp++) {
                uint32_t vh[4], vl[4];
                uint32_t off = (uint32_t)((c * 16 + vb_row) * KPAD + dbp * 16 + vb_col) * 2;
                ldm_x4_t(vh, bVh + off);
                ldm_x4_t(vl, bVl + off);
                mma_bf16(D[2 * dbp],     ph[c], vh);
                mma_bf16(D[2 * dbp],     ph[c], vl);
                mma_bf16(D[2 * dbp],     pl[c], vh);
                mma_bf16(D[2 * dbp + 1], ph[c], vh + 2);
                mma_bf16(D[2 * dbp + 1], ph[c], vl + 2);
                mma_bf16(D[2 * dbp + 1], pl[c], vh + 2);
            }
        }
        __syncthreads();
    }

    float inv0 = 1.0f / lr[0];
    float inv1 = 1.0f / lr[1];
    int row0 = qt * 64 + wid * 16 + g;
#pragma unroll
    for (int db = 0; db < 8; db++) {
        int col = h * HD + db * 8 + 2 * t;
        uint32_t h0, l0, h1, l1;
        split2(D[db][0] * inv0, D[db][1] * inv0, h0, l0);
        split2(D[db][2] * inv1, D[db][3] * inv1, h1, l1);
        *reinterpret_cast<uint32_t*>(g_aoh + (size_t)row0 * DIM + col) = h0;
        *reinterpret_cast<uint32_t*>(g_aol + (size_t)row0 * DIM + col) = l0;
        *reinterpret_cast<uint32_t*>(g_aoh + (size_t)(row0 + 8) * DIM + col) = h1;
        *reinterpret_cast<uint32_t*>(g_aol + (size_t)(row0 + 8) * DIM + col) = l1;
    }
}

// ---------------------------------------------------------------------------
// Launch
// ---------------------------------------------------------------------------
extern "C" void kernel_launch(void* const* d_in, const int* in_sizes, int n_in,
                              void* d_out, int out_size) {
    const float* x  = (const float*)d_in[0];
    const float* wq = (const float*)d_in[1];
    const float* wk = (const float*)d_in[2];
    const float* wv = (const float*)d_in[3];
    const float* wo = (const float*)d_in[4];
    float* out = (float*)d_out;

    static bool configured = false;
    if (!configured) {
        cudaFuncSetAttribute(qkv_gemm,
                             cudaFuncAttributeMaxDynamicSharedMemorySize, GEMM_SMEM);
        cudaFuncSetAttribute(o_gemm,
                             cudaFuncAttributeMaxDynamicSharedMemorySize, GEMM_SMEM);
        cudaFuncSetAttribute(attn_tc_kernel,
                             cudaFuncAttributeMaxDynamicSharedMemorySize, ATTN_SMEM);
        configured = true;
    }

    rope_table_kernel<<<S_LEN, 32>>>();
    conv_split_all<<<(C5 + 255) / 256, 256>>>(
        (const float4*)x, (const float4*)wq, (const float4*)wk,
        (const float4*)wv, (const float4*)wo);
    qkv_gemm<<<dim3(24, 16), 256, GEMM_SMEM>>>();
    attn_tc_kernel<<<dim3(S_LEN / 64, NH), 128, ATTN_SMEM>>>();
    o_gemm<<<dim3(16, 16), 256, GEMM_SMEM>>>(out);
}

// round 12
// speedup vs baseline: 1.0612x; 1.0612x over previous
#include <cuda_runtime.h>
#include <cuda_bf16.h>
#include <math.h>
#include <stdint.h>

#define S_LEN 2048
#define DIM 2048
#define NH 32
#define NKV 8
#define HD 64
#define KVDIM (NKV * HD)   // 512

// ---------------------------------------------------------------------------
// Scratch (bf16 hi/lo pairs stored as uint16)
// ---------------------------------------------------------------------------
__device__ __align__(16) uint16_t g_xh[S_LEN * DIM],  g_xl[S_LEN * DIM];
__device__ __align__(16) uint16_t g_wqh[DIM * DIM],   g_wql[DIM * DIM];
__device__ __align__(16) uint16_t g_wkh[KVDIM * DIM], g_wkl[KVDIM * DIM];
__device__ __align__(16) uint16_t g_wvh[KVDIM * DIM], g_wvl[KVDIM * DIM];
__device__ __align__(16) uint16_t g_woh[DIM * DIM],   g_wol[DIM * DIM];
__device__ __align__(16) uint16_t g_qh[S_LEN * DIM],  g_ql[S_LEN * DIM];
__device__ __align__(16) uint16_t g_kh[S_LEN * KVDIM], g_kl[S_LEN * KVDIM];
__device__ __align__(16) uint16_t g_vh[S_LEN * KVDIM], g_vl[S_LEN * KVDIM];
__device__ __align__(16) uint16_t g_aoh[S_LEN * DIM], g_aol[S_LEN * DIM];
__device__ float g_ct[S_LEN * 32];
__device__ float g_st[S_LEN * 32];

// ---------------------------------------------------------------------------
// helpers
// ---------------------------------------------------------------------------
__device__ __forceinline__ uint32_t smem_u32(const void* p) {
    uint32_t a;
    asm("{ .reg .u64 t; cvta.to.shared.u64 t, %1; cvt.u32.u64 %0, t; }"
        : "=r"(a) : "l"(p));
    return a;
}
__device__ __forceinline__ void ldm_x4(uint32_t* r, uint32_t addr) {
    asm volatile("ldmatrix.sync.aligned.m8n8.x4.shared.b16 {%0,%1,%2,%3}, [%4];"
                 : "=r"(r[0]), "=r"(r[1]), "=r"(r[2]), "=r"(r[3]) : "r"(addr));
}
__device__ __forceinline__ void ldm_x4_t(uint32_t* r, uint32_t addr) {
    asm volatile("ldmatrix.sync.aligned.m8n8.x4.trans.shared.b16 {%0,%1,%2,%3}, [%4];"
                 : "=r"(r[0]), "=r"(r[1]), "=r"(r[2]), "=r"(r[3]) : "r"(addr));
}
__device__ __forceinline__ void mma_bf16(float* d, const uint32_t* a,
                                         const uint32_t* b) {
    asm volatile(
        "mma.sync.aligned.m16n8k16.row.col.f32.bf16.bf16.f32 "
        "{%0,%1,%2,%3}, {%4,%5,%6,%7}, {%8,%9}, {%0,%1,%2,%3};"
        : "+f"(d[0]), "+f"(d[1]), "+f"(d[2]), "+f"(d[3])
        : "r"(a[0]), "r"(a[1]), "r"(a[2]), "r"(a[3]), "r"(b[0]), "r"(b[1]));
}
__device__ __forceinline__ void split2(float x, float y, uint32_t& hi, uint32_t& lo) {
    __nv_bfloat162 h = __float22bfloat162_rn(make_float2(x, y));
    hi = *reinterpret_cast<uint32_t*>(&h);
    __nv_bfloat162 l = __float22bfloat162_rn(make_float2(
        x - __bfloat162float(h.x), y - __bfloat162float(h.y)));
    lo = *reinterpret_cast<uint32_t*>(&l);
}

#define CP_ASYNC16(dst_u32, gsrc) \
    asm volatile("cp.async.cg.shared.global [%0], [%1], 16;" \
                 :: "r"(dst_u32), "l"(gsrc) : "memory")
#define CP_COMMIT() asm volatile("cp.async.commit_group;" ::: "memory")
#define CP_WAIT(n)  asm volatile("cp.async.wait_group %0;" :: "n"(n) : "memory")

// ---------------------------------------------------------------------------
// Fused fp32 -> bf16 hi/lo split for all five inputs (one launch)
// ---------------------------------------------------------------------------
#define N4_X  (S_LEN * DIM / 4)
#define N4_WQ (DIM * DIM / 4)
#define N4_WK (KVDIM * DIM / 4)
#define N4_WV (KVDIM * DIM / 4)
#define N4_WO (DIM * DIM / 4)
#define C1 (N4_X)
#define C2 (C1 + N4_WQ)
#define C3 (C2 + N4_WK)
#define C4 (C3 + N4_WV)
#define C5 (C4 + N4_WO)

__global__ __launch_bounds__(256)
void conv_split_all(const float4* __restrict__ x, const float4* __restrict__ wq,
                    const float4* __restrict__ wk, const float4* __restrict__ wv,
                    const float4* __restrict__ wo) {
    int i = blockIdx.x * 256 + threadIdx.x;
    if (i >= C5) return;
    const float4* src;
    uint2 *dh, *dl;
    int j;
    if (i < C1)      { src = x;  dh = (uint2*)g_xh;  dl = (uint2*)g_xl;  j = i; }
    else if (i < C2) { src = wq; dh = (uint2*)g_wqh; dl = (uint2*)g_wql; j = i - C1; }
    else if (i < C3) { src = wk; dh = (uint2*)g_wkh; dl = (uint2*)g_wkl; j = i - C2; }
    else if (i < C4) { src = wv; dh = (uint2*)g_wvh; dl = (uint2*)g_wvl; j = i - C3; }
    else             { src = wo; dh = (uint2*)g_woh; dl = (uint2*)g_wol; j = i - C4; }
    float4 f = src[j];
    uint2 h, l;
    split2(f.x, f.y, h.x, l.x);
    split2(f.z, f.w, h.y, l.y);
    dh[j] = h;
    dl[j] = l;
}

// ---------------------------------------------------------------------------
// RoPE cos/sin table (verified: fp32 angle, high-precision trig)
// ---------------------------------------------------------------------------
__global__ void rope_table_kernel() {
    int s = blockIdx.x;
    int i = threadIdx.x;
    float e = (float)i / 32.0f;
    float fr = 1.0f / powf(10000.0f, e);
    float angf = (float)s * fr;
    double ang = (double)angf;
    g_ct[s * 32 + i] = (float)cos(ang);
    g_st[s * 32 + i] = (float)sin(ang);
}

// ---------------------------------------------------------------------------
// GEMM core (2-stage cp.async ring: 81920 B smem -> 2 CTAs/SM)
// ---------------------------------------------------------------------------
#define GPAD 40
#define GSZ (128 * GPAD)
#define GEMM_SMEM (8 * GSZ * 2)   // 81920 bytes

__device__ __forceinline__ void gemm_load_chunk(
    uint32_t sb, int stage, int tid, int m0, int bn0, int k0,
    const uint16_t* Ah, const uint16_t* Al,
    const uint16_t* Bh, const uint16_t* Bl, int K) {
    const uint32_t st = sb + (uint32_t)stage * 4 * GSZ * 2;
#pragma unroll
    for (int i = 0; i < 2; i++) {
        int cid = tid + i * 256;
        int r = cid >> 2;
        int c = (cid & 3) * 8;
        uint32_t soff = (uint32_t)(r * GPAD + c) * 2;
        CP_ASYNC16(st + 0 * GSZ * 2 + soff, Ah + (size_t)(m0 + r) * K + k0 + c);
        CP_ASYNC16(st + 1 * GSZ * 2 + soff, Al + (size_t)(m0 + r) * K + k0 + c);
        CP_ASYNC16(st + 2 * GSZ * 2 + soff, Bh + (size_t)(bn0 + r) * K + k0 + c);
        CP_ASYNC16(st + 3 * GSZ * 2 + soff, Bl + (size_t)(bn0 + r) * K + k0 + c);
    }
}

__device__ __forceinline__ void gemm_compute_chunk(
    uint32_t sb, int stage, float acc[2][8][4],
    int wm, int wn, int a_r, int a_c, int b_r, int b_c) {
    const uint32_t st = sb + (uint32_t)stage * 4 * GSZ * 2;
    const uint32_t bAh = st, bAl = st + GSZ * 2;
    const uint32_t bBh = st + 2 * GSZ * 2, bBl = st + 3 * GSZ * 2;
#pragma unroll
    for (int ks = 0; ks < 2; ks++) {
        const int kc = ks * 16;
        uint32_t ah[2][4], al[2][4];
#pragma unroll
        for (int mi = 0; mi < 2; mi++) {
            uint32_t off = (uint32_t)((wm + mi * 16 + a_r) * GPAD + kc + a_c) * 2;
            ldm_x4(ah[mi], bAh + off);
            ldm_x4(al[mi], bAl + off);
        }
        uint32_t bh[8][2], bl[8][2];
#pragma unroll
        for (int nj = 0; nj < 4; nj++) {
            uint32_t off = (uint32_t)((wn + nj * 16 + b_r) * GPAD + kc + b_c) * 2;
            uint32_t t[4];
            ldm_x4(t, bBh + off);
            bh[nj * 2][0] = t[0]; bh[nj * 2][1] = t[1];
            bh[nj * 2 + 1][0] = t[2]; bh[nj * 2 + 1][1] = t[3];
            ldm_x4(t, bBl + off);
            bl[nj * 2][0] = t[0]; bl[nj * 2][1] = t[1];
            bl[nj * 2 + 1][0] = t[2]; bl[nj * 2 + 1][1] = t[3];
        }
#pragma unroll
        for (int mi = 0; mi < 2; mi++)
#pragma unroll
            for (int ni = 0; ni < 8; ni++) {
                mma_bf16(acc[mi][ni], ah[mi], bh[ni]);
                mma_bf16(acc[mi][ni], ah[mi], bl[ni]);
                mma_bf16(acc[mi][ni], al[mi], bh[ni]);
            }
    }
}

// ---------------------------------------------------------------------------
// Fused QKV GEMM + RoPE/scale/split epilogue. Grid (24, 16).
// ---------------------------------------------------------------------------
__global__ __launch_bounds__(256)
void qkv_gemm() {
    extern __shared__ uint16_t dsm[];
    const uint32_t sb = smem_u32(dsm);

    const int tid  = threadIdx.x;
    const int wid  = tid >> 5;
    const int lane = tid & 31;
    const int wm = (wid & 3) * 32;
    const int wn = (wid >> 2) * 64;
    const int m0 = blockIdx.y * 128;
    const int n0 = blockIdx.x * 128;

    const uint16_t *Bh, *Bl;
    int bn0, seg;
    if (n0 < 2048)      { Bh = g_wqh; Bl = g_wql; bn0 = n0;        seg = 0; }
    else if (n0 < 2560) { Bh = g_wkh; Bl = g_wkl; bn0 = n0 - 2048; seg = 1; }
    else                { Bh = g_wvh; Bl = g_wvl; bn0 = n0 - 2560; seg = 2; }

    float acc[2][8][4];
#pragma unroll
    for (int i = 0; i < 2; i++)
#pragma unroll
        for (int j = 0; j < 8; j++)
#pragma unroll
            for (int e = 0; e < 4; e++) acc[i][j][e] = 0.f;

    const int a_r = lane & 15;
    const int a_c = (lane >> 4) << 3;
    const int b_r = (lane & 7) + ((lane >> 4) << 3);
    const int b_c = ((lane >> 3) & 1) << 3;

    gemm_load_chunk(sb, 0, tid, m0, bn0, 0, g_xh, g_xl, Bh, Bl, DIM);
    CP_COMMIT();

    for (int ck = 0; ck < 64; ck++) {
        const int cur = ck & 1;
        CP_WAIT(0);
        __syncthreads();
        if (ck + 1 < 64) {
            gemm_load_chunk(sb, (ck + 1) & 1, tid, m0, bn0, (ck + 1) * 32,
                            g_xh, g_xl, Bh, Bl, DIM);
            CP_COMMIT();
        }
        gemm_compute_chunk(sb, cur, acc, wm, wn, a_r, a_c, b_r, b_c);
    }

    // ---- epilogue ----
    const int g2 = lane >> 2, t2 = lane & 3;
    if (seg < 2) {
        const int W = (seg == 0) ? DIM : KVDIM;
        uint16_t* dsth = (seg == 0) ? g_qh : g_kh;
        uint16_t* dstl = (seg == 0) ? g_ql : g_kl;
        const float scale = (seg == 0) ? 0.125f : 1.0f;
        const int cb = bn0 + wn;
#pragma unroll
        for (int mi = 0; mi < 2; mi++) {
            int r0 = m0 + wm + mi * 16 + g2;
#pragma unroll
            for (int ni = 0; ni < 4; ni++) {
                int jj = ni * 8 + 2 * t2;
                float2 c0 = *reinterpret_cast<const float2*>(g_ct + r0 * 32 + jj);
                float2 s0 = *reinterpret_cast<const float2*>(g_st + r0 * 32 + jj);
                float2 c1 = *reinterpret_cast<const float2*>(g_ct + (r0 + 8) * 32 + jj);
                float2 s1 = *reinterpret_cast<const float2*>(g_st + (r0 + 8) * 32 + jj);
                uint32_t h, l;
                float x1a = acc[mi][ni][0],     x1b = acc[mi][ni][1];
                float x2a = acc[mi][ni + 4][0], x2b = acc[mi][ni + 4][1];
                split2((x1a * c0.x - x2a * s0.x) * scale,
                       (x1b * c0.y - x2b * s0.y) * scale, h, l);
                *reinterpret_cast<uint32_t*>(dsth + (size_t)r0 * W + cb + jj) = h;
                *reinterpret_cast<uint32_t*>(dstl + (size_t)r0 * W + cb + jj) = l;
                split2((x2a * c0.x + x1a * s0.x) * scale,
                       (x2b * c0.y + x1b * s0.y) * scale, h, l);
                *reinterpret_cast<uint32_t*>(dsth + (size_t)r0 * W + cb + jj + 32) = h;
                *reinterpret_cast<uint32_t*>(dstl + (size_t)r0 * W + cb + jj + 32) = l;
                x1a = acc[mi][ni][2];     x1b = acc[mi][ni][3];
                x2a = acc[mi][ni + 4][2]; x2b = acc[mi][ni + 4][3];
                split2((x1a * c1.x - x2a * s1.x) * scale,
                       (x1b * c1.y - x2b * s1.y) * scale, h, l);
                *reinterpret_cast<uint32_t*>(dsth + (size_t)(r0 + 8) * W + cb + jj) = h;
                *reinterpret_cast<uint32_t*>(dstl + (size_t)(r0 + 8) * W + cb + jj) = l;
                split2((x2a * c1.x + x1a * s1.x) * scale,
                       (x2b * c1.y + x1b * s1.y) * scale, h, l);
                *reinterpret_cast<uint32_t*>(dsth + (size_t)(r0 + 8) * W + cb + jj + 32) = h;
                *reinterpret_cast<uint32_t*>(dstl + (size_t)(r0 + 8) * W + cb + jj + 32) = l;
            }
        }
    } else {
        const int cb = bn0 + wn;
#pragma unroll
        for (int mi = 0; mi < 2; mi++) {
            int r0 = m0 + wm + mi * 16 + g2;
#pragma unroll
            for (int ni = 0; ni < 8; ni++) {
                int cc = cb + ni * 8 + 2 * t2;
                uint32_t h, l;
                split2(acc[mi][ni][0], acc[mi][ni][1], h, l);
                *reinterpret_cast<uint32_t*>(g_vh + (size_t)r0 * KVDIM + cc) = h;
                *reinterpret_cast<uint32_t*>(g_vl + (size_t)r0 * KVDIM + cc) = l;
                split2(acc[mi][ni][2], acc[mi][ni][3], h, l);
                *reinterpret_cast<uint32_t*>(g_vh + (size_t)(r0 + 8) * KVDIM + cc) = h;
                *reinterpret_cast<uint32_t*>(g_vl + (size_t)(r0 + 8) * KVDIM + cc) = l;
            }
        }
    }
}

// ---------------------------------------------------------------------------
// O projection GEMM: out = ao @ wo^T, fp32 output.
// ---------------------------------------------------------------------------
__global__ __launch_bounds__(256)
void o_gemm(float* __restrict__ C) {
    extern __shared__ uint16_t dsm[];
    const uint32_t sb = smem_u32(dsm);

    const int tid  = threadIdx.x;
    const int wid  = tid >> 5;
    const int lane = tid & 31;
    const int wm = (wid & 3) * 32;
    const int wn = (wid >> 2) * 64;
    const int m0 = blockIdx.y * 128;
    const int n0 = blockIdx.x * 128;

    float acc[2][8][4];
#pragma unroll
    for (int i = 0; i < 2; i++)
#pragma unroll
        for (int j = 0; j < 8; j++)
#pragma unroll
            for (int e = 0; e < 4; e++) acc[i][j][e] = 0.f;

    const int a_r = lane & 15;
    const int a_c = (lane >> 4) << 3;
    const int b_r = (lane & 7) + ((lane >> 4) << 3);
    const int b_c = ((lane >> 3) & 1) << 3;

    gemm_load_chunk(sb, 0, tid, m0, n0, 0, g_aoh, g_aol, g_woh, g_wol, DIM);
    CP_COMMIT();

    for (int ck = 0; ck < 64; ck++) {
        const int cur = ck & 1;
        CP_WAIT(0);
        __syncthreads();
        if (ck + 1 < 64) {
            gemm_load_chunk(sb, (ck + 1) & 1, tid, m0, n0, (ck + 1) * 32,
                            g_aoh, g_aol, g_woh, g_wol, DIM);
            CP_COMMIT();
        }
        gemm_compute_chunk(sb, cur, acc, wm, wn, a_r, a_c, b_r, b_c);
    }

    const int g2 = lane >> 2, t2 = lane & 3;
#pragma unroll
    for (int mi = 0; mi < 2; mi++) {
        int r0 = m0 + wm + mi * 16 + g2;
#pragma unroll
        for (int ni = 0; ni < 8; ni++) {
            int c = n0 + wn + ni * 8 + t2 * 2;
            *reinterpret_cast<float2*>(C + (size_t)r0 * DIM + c) =
                make_float2(acc[mi][ni][0], acc[mi][ni][1]);
            *reinterpret_cast<float2*>(C + (size_t)(r0 + 8) * DIM + c) =
                make_float2(acc[mi][ni][2], acc[mi][ni][3]);
        }
    }
}

// ---------------------------------------------------------------------------
// Tensor-core flash attention: 256 threads / 128 q-rows per CTA,
// 2-stage cp.async K/V ring. Grid (16 qtiles, 32 heads).
// Warp w owns q-rows w*16..w*16+15 of the 128-row tile.
// ---------------------------------------------------------------------------
#define KPAD 72
#define AARR (64 * KPAD * 2)      // bytes per array per stage (9216)
#define ASTG (4 * AARR)           // bytes per stage (36864)
#define ATTN_SMEM (2 * ASTG)      // 73728
#define LOG2E 1.4426950408889634f

__global__ __launch_bounds__(256, 2)
void attn_tc_kernel() {
    extern __shared__ uint16_t asm_[];
    const uint32_t sb = smem_u32(asm_);

    const int qt = (int)gridDim.x - 1 - (int)blockIdx.x;   // heavy tiles first
    const int h  = blockIdx.y;
    const int kvh = h >> 2;
    const int tid = threadIdx.x;
    const int wid = tid >> 5;       // 0..7
    const int lane = tid & 31;
    const int g = lane >> 2;
    const int t = lane & 3;

    // ---- stage Q (128 rows) into both stages' Kh/Kl regions ----
    // row r: stage r>>6, local row r&63
#pragma unroll
    for (int it = 0; it < 4; it++) {
        int cid = tid + it * 256;       // 0..1023 = 128 rows x 8 chunks
        int r = cid >> 3;
        int c = (cid & 7) * 8;
        int stg = r >> 6, lr = r & 63;
        uint32_t base = (uint32_t)stg * (ASTG / 2);
        *reinterpret_cast<uint4*>(&asm_[base + lr * KPAD + c]) =
            *reinterpret_cast<const uint4*>(
                g_qh + (size_t)(qt * 128 + r) * DIM + h * HD + c);
        *reinterpret_cast<uint4*>(&asm_[base + (AARR / 2) + lr * KPAD + c]) =
            *reinterpret_cast<const uint4*>(
                g_ql + (size_t)(qt * 128 + r) * DIM + h * HD + c);
    }
    __syncthreads();

    uint32_t qh[4][4], ql[4][4];
    {
        int srow = wid * 16 + (lane & 15);      // 0..127
        int stg = srow >> 6, lrow = srow & 63;
        int col = ((lane >> 4) & 1) * 8;
        uint32_t base = sb + (uint32_t)stg * ASTG;
#pragma unroll
        for (int c = 0; c < 4; c++) {
            uint32_t off = (uint32_t)(lrow * KPAD + c * 16 + col) * 2;
            ldm_x4(qh[c], base + off);
            ldm_x4(ql[c], base + AARR + off);
        }
    }
    __syncthreads();

    float mr[2] = {-INFINITY, -INFINITY};
    float lr[2] = {0.f, 0.f};
    float D[8][4];
#pragma unroll
    for (int i = 0; i < 8; i++)
#pragma unroll
        for (int j = 0; j < 4; j++) D[i][j] = 0.f;

    const int kb_row = (lane & 7) + ((lane >> 4) << 3);
    const int kb_col = ((lane >> 3) & 1) * 8;
    const int vb_row = (lane & 7) + (((lane >> 3) & 1) << 3);
    const int vb_col = ((lane >> 4) & 1) * 8;

    auto stage_kv = [&](int kt, int stage) {
        const uint32_t st = sb + (uint32_t)stage * ASTG;
#pragma unroll
        for (int it = 0; it < 2; it++) {
            int cid = tid + it * 256;      // 0..511 = 64 rows x 8 chunks
            int r = cid >> 3;
            int c = (cid & 7) * 8;
            size_t off = (size_t)(kt * 64 + r) * KVDIM + kvh * HD + c;
            uint32_t soff = (uint32_t)(r * KPAD + c) * 2;
            CP_ASYNC16(st + 0 * AARR + soff, g_kh + off);
            CP_ASYNC16(st + 1 * AARR + soff, g_kl + off);
            CP_ASYNC16(st + 2 * AARR + soff, g_vh + off);
            CP_ASYNC16(st + 3 * AARR + soff, g_vl + off);
        }
    };

    const int ktmax = 2 * qt + 1;    // inclusive; keys up to (qt+1)*128-1
    stage_kv(0, 0);
    CP_COMMIT();

    for (int kt = 0; kt <= ktmax; kt++) {
        const uint32_t st = sb + (uint32_t)(kt & 1) * ASTG;
        const uint32_t bKh = st, bKl = st + AARR;
        const uint32_t bVh = st + 2 * AARR, bVl = st + 3 * AARR;

        CP_WAIT(0);
        __syncthreads();
        if (kt < ktmax) {
            stage_kv(kt + 1, (kt + 1) & 1);
            CP_COMMIT();
        }

        float S[8][4];
#pragma unroll
        for (int i = 0; i < 8; i++)
#pragma unroll
            for (int j = 0; j < 4; j++) S[i][j] = 0.f;

#pragma unroll
        for (int c = 0; c < 4; c++) {
#pragma unroll
            for (int nbp = 0; nbp < 4; nbp++) {
                uint32_t kh[4], kl[4];
                uint32_t off = (uint32_t)((nbp * 16 + kb_row) * KPAD + c * 16 + kb_col) * 2;
                ldm_x4(kh, bKh + off);
                ldm_x4(kl, bKl + off);
                mma_bf16(S[2 * nbp],     qh[c], kh);
                mma_bf16(S[2 * nbp],     qh[c], kl);
                mma_bf16(S[2 * nbp],     ql[c], kh);
                mma_bf16(S[2 * nbp + 1], qh[c], kh + 2);
                mma_bf16(S[2 * nbp + 1], qh[c], kl + 2);
                mma_bf16(S[2 * nbp + 1], ql[c], kh + 2);
            }
        }

        // causal mask: needed only when this k-tile can exceed warp's rows
        const int rbase = qt * 128 + wid * 16;
        if (kt * 64 + 63 > rbase) {
            int r0g = rbase + g;
#pragma unroll
            for (int nb = 0; nb < 8; nb++) {
                int c0 = kt * 64 + nb * 8 + 2 * t;
                if (c0 > r0g)     S[nb][0] = -INFINITY;
                if (c0 + 1 > r0g) S[nb][1] = -INFINITY;
                if (c0 > r0g + 8)     S[nb][2] = -INFINITY;
                if (c0 + 1 > r0g + 8) S[nb][3] = -INFINITY;
            }
        }

        float mx0 = -INFINITY, mx1 = -INFINITY;
#pragma unroll
        for (int nb = 0; nb < 8; nb++) {
            mx0 = fmaxf(mx0, fmaxf(S[nb][0], S[nb][1]));
            mx1 = fmaxf(mx1, fmaxf(S[nb][2], S[nb][3]));
        }
        mx0 = fmaxf(mx0, __shfl_xor_sync(0xffffffffu, mx0, 1));
        mx0 = fmaxf(mx0, __shfl_xor_sync(0xffffffffu, mx0, 2));
        mx1 = fmaxf(mx1, __shfl_xor_sync(0xffffffffu, mx1, 1));
        mx1 = fmaxf(mx1, __shfl_xor_sync(0xffffffffu, mx1, 2));
        float newm0 = fmaxf(mr[0], mx0);
        float newm1 = fmaxf(mr[1], mx1);
        float a0 = exp2f((mr[0] - newm0) * LOG2E);
        float a1 = exp2f((mr[1] - newm1) * LOG2E);
        mr[0] = newm0; mr[1] = newm1;

        float sum0 = 0.f, sum1 = 0.f;
#pragma unroll
        for (int nb = 0; nb < 8; nb++) {
            S[nb][0] = exp2f((S[nb][0] - newm0) * LOG2E);
            S[nb][1] = exp2f((S[nb][1] - newm0) * LOG2E);
            S[nb][2] = exp2f((S[nb][2] - newm1) * LOG2E);
            S[nb][3] = exp2f((S[nb][3] - newm1) * LOG2E);
            sum0 += S[nb][0] + S[nb][1];
            sum1 += S[nb][2] + S[nb][3];
        }
        sum0 += __shfl_xor_sync(0xffffffffu, sum0, 1);
        sum0 += __shfl_xor_sync(0xffffffffu, sum0, 2);
        sum1 += __shfl_xor_sync(0xffffffffu, sum1, 1);
        sum1 += __shfl_xor_sync(0xffffffffu, sum1, 2);
        lr[0] = lr[0] * a0 + sum0;
        lr[1] = lr[1] * a1 + sum1;

        uint32_t ph[4][4], pl[4][4];
#pragma unroll
        for (int c = 0; c < 4; c++) {
            int nA = 2 * c, nB = 2 * c + 1;
            split2(S[nA][0], S[nA][1], ph[c][0], pl[c][0]);
            split2(S[nA][2], S[nA][3], ph[c][1], pl[c][1]);
            split2(S[nB][0], S[nB][1], ph[c][2], pl[c][2]);
            split2(S[nB][2], S[nB][3], ph[c][3], pl[c][3]);
        }

#pragma unroll
        for (int db = 0; db < 8; db++) {
            D[db][0] *= a0; D[db][1] *= a0;
            D[db][2] *= a1; D[db][3] *= a1;
        }

#pragma unroll
        for (int c = 0; c < 4; c++) {
#pragma unroll
            for (int dbp = 0; dbp < 4; dbp++) {
                uint32_t vh[4], vl[4];
                uint32_t off = (uint32_t)((c * 16 + vb_row) * KPAD + dbp * 16 + vb_col) * 2;
                ldm_x4_t(vh, bVh + off);
                ldm_x4_t(vl, bVl + off);
                mma_bf16(D[2 * dbp],     ph[c], vh);
                mma_bf16(D[2 * dbp],     ph[c], vl);
                mma_bf16(D[2 * dbp],     pl[c], vh);
                mma_bf16(D[2 * dbp + 1], ph[c], vh + 2);
                mma_bf16(D[2 * dbp + 1], ph[c], vl + 2);
                mma_bf16(D[2 * dbp + 1], pl[c], vh + 2);
            }
        }
        __syncthreads();
    }

    float inv0 = 1.0f / lr[0];
    float inv1 = 1.0f / lr[1];
    int row0 = qt * 128 + wid * 16 + g;
#pragma unroll
    for (int db = 0; db < 8; db++) {
        int col = h * HD + db * 8 + 2 * t;
        uint32_t h0, l0, h1, l1;
        split2(D[db][0] * inv0, D[db][1] * inv0, h0, l0);
        split2(D[db][2] * inv1, D[db][3] * inv1, h1, l1);
        *reinterpret_cast<uint32_t*>(g_aoh + (size_t)row0 * DIM + col) = h0;
        *reinterpret_cast<uint32_t*>(g_aol + (size_t)row0 * DIM + col) = l0;
        *reinterpret_cast<uint32_t*>(g_aoh + (size_t)(row0 + 8) * DIM + col) = h1;
        *reinterpret_cast<uint32_t*>(g_aol + (size_t)(row0 + 8) * DIM + col) = l1;
    }
}

// ---------------------------------------------------------------------------
// Launch
// ---------------------------------------------------------------------------
extern "C" void kernel_launch(void* const* d_in, const int* in_sizes, int n_in,
                              void* d_out, int out_size) {
    const float* x  = (const float*)d_in[0];
    const float* wq = (const float*)d_in[1];
    const float* wk = (const float*)d_in[2];
    const float* wv = (const float*)d_in[3];
    const float* wo = (const float*)d_in[4];
    float* out = (float*)d_out;

    static bool configured = false;
    if (!configured) {
        cudaFuncSetAttribute(qkv_gemm,
                             cudaFuncAttributeMaxDynamicSharedMemorySize, GEMM_SMEM);
        cudaFuncSetAttribute(o_gemm,
                             cudaFuncAttributeMaxDynamicSharedMemorySize, GEMM_SMEM);
        cudaFuncSetAttribute(attn_tc_kernel,
                             cudaFuncAttributeMaxDynamicSharedMemorySize, ATTN_SMEM);
        configured = true;
    }

    rope_table_kernel<<<S_LEN, 32>>>();
    conv_split_all<<<(C5 + 255) / 256, 256>>>(
        (const float4*)x, (const float4*)wq, (const float4*)wk,
        (const float4*)wv, (const float4*)wo);
    qkv_gemm<<<dim3(24, 16), 256, GEMM_SMEM>>>();
    attn_tc_kernel<<<dim3(S_LEN / 128, NH), 256, ATTN_SMEM>>>();
    o_gemm<<<dim3(16, 16), 256, GEMM_SMEM>>>(out);
}

// round 13
// speedup vs baseline: 1.1210x; 1.0564x over previous
#include <cuda_runtime.h>
#include <cuda_bf16.h>
#include <math.h>
#include <stdint.h>

#define S_LEN 2048
#define DIM 2048
#define NH 32
#define NKV 8
#define HD 64
#define KVDIM (NKV * HD)   // 512

// ---------------------------------------------------------------------------
// Scratch (bf16 hi/lo pairs stored as uint16)
// ---------------------------------------------------------------------------
__device__ __align__(16) uint16_t g_xh[S_LEN * DIM],  g_xl[S_LEN * DIM];
__device__ __align__(16) uint16_t g_wqh[DIM * DIM],   g_wql[DIM * DIM];
__device__ __align__(16) uint16_t g_wkh[KVDIM * DIM], g_wkl[KVDIM * DIM];
__device__ __align__(16) uint16_t g_wvh[KVDIM * DIM], g_wvl[KVDIM * DIM];
__device__ __align__(16) uint16_t g_woh[DIM * DIM],   g_wol[DIM * DIM];
__device__ __align__(16) uint16_t g_qh[S_LEN * DIM],  g_ql[S_LEN * DIM];
__device__ __align__(16) uint16_t g_kh[S_LEN * KVDIM], g_kl[S_LEN * KVDIM];
__device__ __align__(16) uint16_t g_vh[S_LEN * KVDIM], g_vl[S_LEN * KVDIM];
__device__ __align__(16) uint16_t g_aoh[S_LEN * DIM], g_aol[S_LEN * DIM];
__device__ float g_ct[S_LEN * 32];
__device__ float g_st[S_LEN * 32];

// ---------------------------------------------------------------------------
// helpers
// ---------------------------------------------------------------------------
__device__ __forceinline__ uint32_t smem_u32(const void* p) {
    uint32_t a;
    asm("{ .reg .u64 t; cvta.to.shared.u64 t, %1; cvt.u32.u64 %0, t; }"
        : "=r"(a) : "l"(p));
    return a;
}
__device__ __forceinline__ void ldm_x4(uint32_t* r, uint32_t addr) {
    asm volatile("ldmatrix.sync.aligned.m8n8.x4.shared.b16 {%0,%1,%2,%3}, [%4];"
                 : "=r"(r[0]), "=r"(r[1]), "=r"(r[2]), "=r"(r[3]) : "r"(addr));
}
__device__ __forceinline__ void ldm_x4_t(uint32_t* r, uint32_t addr) {
    asm volatile("ldmatrix.sync.aligned.m8n8.x4.trans.shared.b16 {%0,%1,%2,%3}, [%4];"
                 : "=r"(r[0]), "=r"(r[1]), "=r"(r[2]), "=r"(r[3]) : "r"(addr));
}
__device__ __forceinline__ void mma_bf16(float* d, const uint32_t* a,
                                         const uint32_t* b) {
    asm volatile(
        "mma.sync.aligned.m16n8k16.row.col.f32.bf16.bf16.f32 "
        "{%0,%1,%2,%3}, {%4,%5,%6,%7}, {%8,%9}, {%0,%1,%2,%3};"
        : "+f"(d[0]), "+f"(d[1]), "+f"(d[2]), "+f"(d[3])
        : "r"(a[0]), "r"(a[1]), "r"(a[2]), "r"(a[3]), "r"(b[0]), "r"(b[1]));
}
__device__ __forceinline__ void split2(float x, float y, uint32_t& hi, uint32_t& lo) {
    __nv_bfloat162 h = __float22bfloat162_rn(make_float2(x, y));
    hi = *reinterpret_cast<uint32_t*>(&h);
    __nv_bfloat162 l = __float22bfloat162_rn(make_float2(
        x - __bfloat162float(h.x), y - __bfloat162float(h.y)));
    lo = *reinterpret_cast<uint32_t*>(&l);
}

#define CP_ASYNC16(dst_u32, gsrc) \
    asm volatile("cp.async.cg.shared.global [%0], [%1], 16;" \
                 :: "r"(dst_u32), "l"(gsrc) : "memory")
#define CP_COMMIT() asm volatile("cp.async.commit_group;" ::: "memory")
#define CP_WAIT(n)  asm volatile("cp.async.wait_group %0;" :: "n"(n) : "memory")

// ---------------------------------------------------------------------------
// Fused fp32 -> bf16 hi/lo split for all five inputs (one launch)
// ---------------------------------------------------------------------------
#define N4_X  (S_LEN * DIM / 4)
#define N4_WQ (DIM * DIM / 4)
#define N4_WK (KVDIM * DIM / 4)
#define N4_WV (KVDIM * DIM / 4)
#define N4_WO (DIM * DIM / 4)
#define C1 (N4_X)
#define C2 (C1 + N4_WQ)
#define C3 (C2 + N4_WK)
#define C4 (C3 + N4_WV)
#define C5 (C4 + N4_WO)

__global__ __launch_bounds__(256)
void conv_split_all(const float4* __restrict__ x, const float4* __restrict__ wq,
                    const float4* __restrict__ wk, const float4* __restrict__ wv,
                    const float4* __restrict__ wo) {
    int i = blockIdx.x * 256 + threadIdx.x;
    if (i >= C5) return;
    const float4* src;
    uint2 *dh, *dl;
    int j;
    if (i < C1)      { src = x;  dh = (uint2*)g_xh;  dl = (uint2*)g_xl;  j = i; }
    else if (i < C2) { src = wq; dh = (uint2*)g_wqh; dl = (uint2*)g_wql; j = i - C1; }
    else if (i < C3) { src = wk; dh = (uint2*)g_wkh; dl = (uint2*)g_wkl; j = i - C2; }
    else if (i < C4) { src = wv; dh = (uint2*)g_wvh; dl = (uint2*)g_wvl; j = i - C3; }
    else             { src = wo; dh = (uint2*)g_woh; dl = (uint2*)g_wol; j = i - C4; }
    float4 f = src[j];
    uint2 h, l;
    split2(f.x, f.y, h.x, l.x);
    split2(f.z, f.w, h.y, l.y);
    dh[j] = h;
    dl[j] = l;
}

// ---------------------------------------------------------------------------
// RoPE cos/sin table (verified: fp32 angle, high-precision trig)
// ---------------------------------------------------------------------------
__global__ void rope_table_kernel() {
    int s = blockIdx.x;
    int i = threadIdx.x;
    float e = (float)i / 32.0f;
    float fr = 1.0f / powf(10000.0f, e);
    float angf = (float)s * fr;
    double ang = (double)angf;
    g_ct[s * 32 + i] = (float)cos(ang);
    g_st[s * 32 + i] = (float)sin(ang);
}

// ---------------------------------------------------------------------------
// GEMM core (2-stage cp.async ring: 81920 B smem -> 2 CTAs/SM)
// ---------------------------------------------------------------------------
#define GPAD 40
#define GSZ (128 * GPAD)
#define GEMM_SMEM (8 * GSZ * 2)   // 81920 bytes

__device__ __forceinline__ void gemm_load_chunk(
    uint32_t sb, int stage, int tid, int m0, int bn0, int k0,
    const uint16_t* Ah, const uint16_t* Al,
    const uint16_t* Bh, const uint16_t* Bl, int K) {
    const uint32_t st = sb + (uint32_t)stage * 4 * GSZ * 2;
#pragma unroll
    for (int i = 0; i < 2; i++) {
        int cid = tid + i * 256;
        int r = cid >> 2;
        int c = (cid & 3) * 8;
        uint32_t soff = (uint32_t)(r * GPAD + c) * 2;
        CP_ASYNC16(st + 0 * GSZ * 2 + soff, Ah + (size_t)(m0 + r) * K + k0 + c);
        CP_ASYNC16(st + 1 * GSZ * 2 + soff, Al + (size_t)(m0 + r) * K + k0 + c);
        CP_ASYNC16(st + 2 * GSZ * 2 + soff, Bh + (size_t)(bn0 + r) * K + k0 + c);
        CP_ASYNC16(st + 3 * GSZ * 2 + soff, Bl + (size_t)(bn0 + r) * K + k0 + c);
    }
}

__device__ __forceinline__ void gemm_compute_chunk(
    uint32_t sb, int stage, float acc[2][8][4],
    int wm, int wn, int a_r, int a_c, int b_r, int b_c) {
    const uint32_t st = sb + (uint32_t)stage * 4 * GSZ * 2;
    const uint32_t bAh = st, bAl = st + GSZ * 2;
    const uint32_t bBh = st + 2 * GSZ * 2, bBl = st + 3 * GSZ * 2;
#pragma unroll
    for (int ks = 0; ks < 2; ks++) {
        const int kc = ks * 16;
        uint32_t ah[2][4], al[2][4];
#pragma unroll
        for (int mi = 0; mi < 2; mi++) {
            uint32_t off = (uint32_t)((wm + mi * 16 + a_r) * GPAD + kc + a_c) * 2;
            ldm_x4(ah[mi], bAh + off);
            ldm_x4(al[mi], bAl + off);
        }
        uint32_t bh[8][2], bl[8][2];
#pragma unroll
        for (int nj = 0; nj < 4; nj++) {
            uint32_t off = (uint32_t)((wn + nj * 16 + b_r) * GPAD + kc + b_c) * 2;
            uint32_t t[4];
            ldm_x4(t, bBh + off);
            bh[nj * 2][0] = t[0]; bh[nj * 2][1] = t[1];
            bh[nj * 2 + 1][0] = t[2]; bh[nj * 2 + 1][1] = t[3];
            ldm_x4(t, bBl + off);
            bl[nj * 2][0] = t[0]; bl[nj * 2][1] = t[1];
            bl[nj * 2 + 1][0] = t[2]; bl[nj * 2 + 1][1] = t[3];
        }
#pragma unroll
        for (int mi = 0; mi < 2; mi++)
#pragma unroll
            for (int ni = 0; ni < 8; ni++) {
                mma_bf16(acc[mi][ni], ah[mi], bh[ni]);
                mma_bf16(acc[mi][ni], ah[mi], bl[ni]);
                mma_bf16(acc[mi][ni], al[mi], bh[ni]);
            }
    }
}

// ---------------------------------------------------------------------------
// Fused QKV GEMM + RoPE/scale/split epilogue. Grid (24, 16).
// ---------------------------------------------------------------------------
__global__ __launch_bounds__(256)
void qkv_gemm() {
    extern __shared__ uint16_t dsm[];
    const uint32_t sb = smem_u32(dsm);

    const int tid  = threadIdx.x;
    const int wid  = tid >> 5;
    const int lane = tid & 31;
    const int wm = (wid & 3) * 32;
    const int wn = (wid >> 2) * 64;
    const int m0 = blockIdx.y * 128;
    const int n0 = blockIdx.x * 128;

    const uint16_t *Bh, *Bl;
    int bn0, seg;
    if (n0 < 2048)      { Bh = g_wqh; Bl = g_wql; bn0 = n0;        seg = 0; }
    else if (n0 < 2560) { Bh = g_wkh; Bl = g_wkl; bn0 = n0 - 2048; seg = 1; }
    else                { Bh = g_wvh; Bl = g_wvl; bn0 = n0 - 2560; seg = 2; }

    float acc[2][8][4];
#pragma unroll
    for (int i = 0; i < 2; i++)
#pragma unroll
        for (int j = 0; j < 8; j++)
#pragma unroll
            for (int e = 0; e < 4; e++) acc[i][j][e] = 0.f;

    const int a_r = lane & 15;
    const int a_c = (lane >> 4) << 3;
    const int b_r = (lane & 7) + ((lane >> 4) << 3);
    const int b_c = ((lane >> 3) & 1) << 3;

    gemm_load_chunk(sb, 0, tid, m0, bn0, 0, g_xh, g_xl, Bh, Bl, DIM);
    CP_COMMIT();

    for (int ck = 0; ck < 64; ck++) {
        const int cur = ck & 1;
        CP_WAIT(0);
        __syncthreads();
        if (ck + 1 < 64) {
            gemm_load_chunk(sb, (ck + 1) & 1, tid, m0, bn0, (ck + 1) * 32,
                            g_xh, g_xl, Bh, Bl, DIM);
            CP_COMMIT();
        }
        gemm_compute_chunk(sb, cur, acc, wm, wn, a_r, a_c, b_r, b_c);
    }

    // ---- epilogue ----
    const int g2 = lane >> 2, t2 = lane & 3;
    if (seg < 2) {
        const int W = (seg == 0) ? DIM : KVDIM;
        uint16_t* dsth = (seg == 0) ? g_qh : g_kh;
        uint16_t* dstl = (seg == 0) ? g_ql : g_kl;
        const float scale = (seg == 0) ? 0.125f : 1.0f;
        const int cb = bn0 + wn;
#pragma unroll
        for (int mi = 0; mi < 2; mi++) {
            int r0 = m0 + wm + mi * 16 + g2;
#pragma unroll
            for (int ni = 0; ni < 4; ni++) {
                int jj = ni * 8 + 2 * t2;
                float2 c0 = *reinterpret_cast<const float2*>(g_ct + r0 * 32 + jj);
                float2 s0 = *reinterpret_cast<const float2*>(g_st + r0 * 32 + jj);
                float2 c1 = *reinterpret_cast<const float2*>(g_ct + (r0 + 8) * 32 + jj);
                float2 s1 = *reinterpret_cast<const float2*>(g_st + (r0 + 8) * 32 + jj);
                uint32_t h, l;
                float x1a = acc[mi][ni][0],     x1b = acc[mi][ni][1];
                float x2a = acc[mi][ni + 4][0], x2b = acc[mi][ni + 4][1];
                split2((x1a * c0.x - x2a * s0.x) * scale,
                       (x1b * c0.y - x2b * s0.y) * scale, h, l);
                *reinterpret_cast<uint32_t*>(dsth + (size_t)r0 * W + cb + jj) = h;
                *reinterpret_cast<uint32_t*>(dstl + (size_t)r0 * W + cb + jj) = l;
                split2((x2a * c0.x + x1a * s0.x) * scale,
                       (x2b * c0.y + x1b * s0.y) * scale, h, l);
                *reinterpret_cast<uint32_t*>(dsth + (size_t)r0 * W + cb + jj + 32) = h;
                *reinterpret_cast<uint32_t*>(dstl + (size_t)r0 * W + cb + jj + 32) = l;
                x1a = acc[mi][ni][2];     x1b = acc[mi][ni][3];
                x2a = acc[mi][ni + 4][2]; x2b = acc[mi][ni + 4][3];
                split2((x1a * c1.x - x2a * s1.x) * scale,
                       (x1b * c1.y - x2b * s1.y) * scale, h, l);
                *reinterpret_cast<uint32_t*>(dsth + (size_t)(r0 + 8) * W + cb + jj) = h;
                *reinterpret_cast<uint32_t*>(dstl + (size_t)(r0 + 8) * W + cb + jj) = l;
                split2((x2a * c1.x + x1a * s1.x) * scale,
                       (x2b * c1.y + x1b * s1.y) * scale, h, l);
                *reinterpret_cast<uint32_t*>(dsth + (size_t)(r0 + 8) * W + cb + jj + 32) = h;
                *reinterpret_cast<uint32_t*>(dstl + (size_t)(r0 + 8) * W + cb + jj + 32) = l;
            }
        }
    } else {
        const int cb = bn0 + wn;
#pragma unroll
        for (int mi = 0; mi < 2; mi++) {
            int r0 = m0 + wm + mi * 16 + g2;
#pragma unroll
            for (int ni = 0; ni < 8; ni++) {
                int cc = cb + ni * 8 + 2 * t2;
                uint32_t h, l;
                split2(acc[mi][ni][0], acc[mi][ni][1], h, l);
                *reinterpret_cast<uint32_t*>(g_vh + (size_t)r0 * KVDIM + cc) = h;
                *reinterpret_cast<uint32_t*>(g_vl + (size_t)r0 * KVDIM + cc) = l;
                split2(acc[mi][ni][2], acc[mi][ni][3], h, l);
                *reinterpret_cast<uint32_t*>(g_vh + (size_t)(r0 + 8) * KVDIM + cc) = h;
                *reinterpret_cast<uint32_t*>(g_vl + (size_t)(r0 + 8) * KVDIM + cc) = l;
            }
        }
    }
}

// ---------------------------------------------------------------------------
// O projection GEMM: out = ao @ wo^T, fp32 output.
// ---------------------------------------------------------------------------
__global__ __launch_bounds__(256)
void o_gemm(float* __restrict__ C) {
    extern __shared__ uint16_t dsm[];
    const uint32_t sb = smem_u32(dsm);

    const int tid  = threadIdx.x;
    const int wid  = tid >> 5;
    const int lane = tid & 31;
    const int wm = (wid & 3) * 32;
    const int wn = (wid >> 2) * 64;
    const int m0 = blockIdx.y * 128;
    const int n0 = blockIdx.x * 128;

    float acc[2][8][4];
#pragma unroll
    for (int i = 0; i < 2; i++)
#pragma unroll
        for (int j = 0; j < 8; j++)
#pragma unroll
            for (int e = 0; e < 4; e++) acc[i][j][e] = 0.f;

    const int a_r = lane & 15;
    const int a_c = (lane >> 4) << 3;
    const int b_r = (lane & 7) + ((lane >> 4) << 3);
    const int b_c = ((lane >> 3) & 1) << 3;

    gemm_load_chunk(sb, 0, tid, m0, n0, 0, g_aoh, g_aol, g_woh, g_wol, DIM);
    CP_COMMIT();

    for (int ck = 0; ck < 64; ck++) {
        const int cur = ck & 1;
        CP_WAIT(0);
        __syncthreads();
        if (ck + 1 < 64) {
            gemm_load_chunk(sb, (ck + 1) & 1, tid, m0, n0, (ck + 1) * 32,
                            g_aoh, g_aol, g_woh, g_wol, DIM);
            CP_COMMIT();
        }
        gemm_compute_chunk(sb, cur, acc, wm, wn, a_r, a_c, b_r, b_c);
    }

    const int g2 = lane >> 2, t2 = lane & 3;
#pragma unroll
    for (int mi = 0; mi < 2; mi++) {
        int r0 = m0 + wm + mi * 16 + g2;
#pragma unroll
        for (int ni = 0; ni < 8; ni++) {
            int c = n0 + wn + ni * 8 + t2 * 2;
            *reinterpret_cast<float2*>(C + (size_t)r0 * DIM + c) =
                make_float2(acc[mi][ni][0], acc[mi][ni][1]);
            *reinterpret_cast<float2*>(C + (size_t)(r0 + 8) * DIM + c) =
                make_float2(acc[mi][ni][2], acc[mi][ni][3]);
        }
    }
}

// ---------------------------------------------------------------------------
// Tensor-core flash attention (R11 config: 128 threads / 64 q-rows,
// 2-stage cp.async K/V ring), launch_bounds(128,3) for 3 CTAs/SM.
// Grid (32 qtiles, 32 heads).
// ---------------------------------------------------------------------------
#define KPAD 72
#define AARR (64 * KPAD * 2)      // bytes per array per stage (9216)
#define ASTG (4 * AARR)           // bytes per stage (36864)
#define ATTN_SMEM (2 * ASTG)      // 73728
#define LOG2E 1.4426950408889634f

__global__ __launch_bounds__(128, 3)
void attn_tc_kernel() {
    extern __shared__ uint16_t asm_[];
    const uint32_t sb = smem_u32(asm_);

    const int qt = (int)gridDim.x - 1 - (int)blockIdx.x;
    const int h  = blockIdx.y;
    const int kvh = h >> 2;
    const int tid = threadIdx.x;
    const int wid = tid >> 5;
    const int lane = tid & 31;
    const int g = lane >> 2;
    const int t = lane & 3;

    // ---- stage Q into stage-0 Kh/Kl region, pull fragments ----
#pragma unroll
    for (int it = 0; it < 4; it++) {
        int cid = tid + it * 128;
        int r = cid >> 3;
        int c = (cid & 7) * 8;
        *reinterpret_cast<uint4*>(&asm_[(0 * AARR / 2) + r * KPAD + c]) =
            *reinterpret_cast<const uint4*>(
                g_qh + (size_t)(qt * 64 + r) * DIM + h * HD + c);
        *reinterpret_cast<uint4*>(&asm_[(1 * AARR / 2) + r * KPAD + c]) =
            *reinterpret_cast<const uint4*>(
                g_ql + (size_t)(qt * 64 + r) * DIM + h * HD + c);
    }
    __syncthreads();

    uint32_t qh[4][4], ql[4][4];
    {
        int row = wid * 16 + (lane & 15);
        int col = ((lane >> 4) & 1) * 8;
#pragma unroll
        for (int c = 0; c < 4; c++) {
            uint32_t off = (uint32_t)(row * KPAD + c * 16 + col) * 2;
            ldm_x4(qh[c], sb + 0 * AARR + off);
            ldm_x4(ql[c], sb + 1 * AARR + off);
        }
    }
    __syncthreads();

    float mr[2] = {-INFINITY, -INFINITY};
    float lr[2] = {0.f, 0.f};
    float D[8][4];
#pragma unroll
    for (int i = 0; i < 8; i++)
#pragma unroll
        for (int j = 0; j < 4; j++) D[i][j] = 0.f;

    const int kb_row = (lane & 7) + ((lane >> 4) << 3);
    const int kb_col = ((lane >> 3) & 1) * 8;
    const int vb_row = (lane & 7) + (((lane >> 3) & 1) << 3);
    const int vb_col = ((lane >> 4) & 1) * 8;

    auto stage_kv = [&](int kt, int stage) {
        const uint32_t st = sb + (uint32_t)stage * ASTG;
#pragma unroll
        for (int it = 0; it < 4; it++) {
            int cid = tid + it * 128;
            int r = cid >> 3;
            int c = (cid & 7) * 8;
            size_t off = (size_t)(kt * 64 + r) * KVDIM + kvh * HD + c;
            uint32_t soff = (uint32_t)(r * KPAD + c) * 2;
            CP_ASYNC16(st + 0 * AARR + soff, g_kh + off);
            CP_ASYNC16(st + 1 * AARR + soff, g_kl + off);
            CP_ASYNC16(st + 2 * AARR + soff, g_vh + off);
            CP_ASYNC16(st + 3 * AARR + soff, g_vl + off);
        }
    };

    stage_kv(0, 0);
    CP_COMMIT();

    for (int kt = 0; kt <= qt; kt++) {
        const uint32_t st = sb + (uint32_t)(kt & 1) * ASTG;
        const uint32_t bKh = st, bKl = st + AARR;
        const uint32_t bVh = st + 2 * AARR, bVl = st + 3 * AARR;

        CP_WAIT(0);
        __syncthreads();
        if (kt < qt) {
            stage_kv(kt + 1, (kt + 1) & 1);
            CP_COMMIT();
        }

        float S[8][4];
#pragma unroll
        for (int i = 0; i < 8; i++)
#pragma unroll
            for (int j = 0; j < 4; j++) S[i][j] = 0.f;

#pragma unroll
        for (int c = 0; c < 4; c++) {
#pragma unroll
            for (int nbp = 0; nbp < 4; nbp++) {
                uint32_t kh[4], kl[4];
                uint32_t off = (uint32_t)((nbp * 16 + kb_row) * KPAD + c * 16 + kb_col) * 2;
                ldm_x4(kh, bKh + off);
                ldm_x4(kl, bKl + off);
                mma_bf16(S[2 * nbp],     qh[c], kh);
                mma_bf16(S[2 * nbp],     qh[c], kl);
                mma_bf16(S[2 * nbp],     ql[c], kh);
                mma_bf16(S[2 * nbp + 1], qh[c], kh + 2);
                mma_bf16(S[2 * nbp + 1], qh[c], kl + 2);
                mma_bf16(S[2 * nbp + 1], ql[c], kh + 2);
            }
        }

        if (kt == qt) {
            int r0 = wid * 16 + g;
#pragma unroll
            for (int nb = 0; nb < 8; nb++) {
                int c0 = nb * 8 + 2 * t;
                if (c0 > r0)     S[nb][0] = -INFINITY;
                if (c0 + 1 > r0) S[nb][1] = -INFINITY;
                if (c0 > r0 + 8)     S[nb][2] = -INFINITY;
                if (c0 + 1 > r0 + 8) S[nb][3] = -INFINITY;
            }
        }

        float mx0 = -INFINITY, mx1 = -INFINITY;
#pragma unroll
        for (int nb = 0; nb < 8; nb++) {
            mx0 = fmaxf(mx0, fmaxf(S[nb][0], S[nb][1]));
            mx1 = fmaxf(mx1, fmaxf(S[nb][2], S[nb][3]));
        }
        mx0 = fmaxf(mx0, __shfl_xor_sync(0xffffffffu, mx0, 1));
        mx0 = fmaxf(mx0, __shfl_xor_sync(0xffffffffu, mx0, 2));
        mx1 = fmaxf(mx1, __shfl_xor_sync(0xffffffffu, mx1, 1));
        mx1 = fmaxf(mx1, __shfl_xor_sync(0xffffffffu, mx1, 2));
        float newm0 = fmaxf(mr[0], mx0);
        float newm1 = fmaxf(mr[1], mx1);
        float a0 = exp2f((mr[0] - newm0) * LOG2E);
        float a1 = exp2f((mr[1] - newm1) * LOG2E);
        mr[0] = newm0; mr[1] = newm1;

        float sum0 = 0.f, sum1 = 0.f;
#pragma unroll
        for (int nb = 0; nb < 8; nb++) {
            S[nb][0] = exp2f((S[nb][0] - newm0) * LOG2E);
            S[nb][1] = exp2f((S[nb][1] - newm0) * LOG2E);
            S[nb][2] = exp2f((S[nb][2] - newm1) * LOG2E);
            S[nb][3] = exp2f((S[nb][3] - newm1) * LOG2E);
            sum0 += S[nb][0] + S[nb][1];
            sum1 += S[nb][2] + S[nb][3];
        }
        sum0 += __shfl_xor_sync(0xffffffffu, sum0, 1);
        sum0 += __shfl_xor_sync(0xffffffffu, sum0, 2);
        sum1 += __shfl_xor_sync(0xffffffffu, sum1, 1);
        sum1 += __shfl_xor_sync(0xffffffffu, sum1, 2);
        lr[0] = lr[0] * a0 + sum0;
        lr[1] = lr[1] * a1 + sum1;

        uint32_t ph[4][4], pl[4][4];
#pragma unroll
        for (int c = 0; c < 4; c++) {
            int nA = 2 * c, nB = 2 * c + 1;
            split2(S[nA][0], S[nA][1], ph[c][0], pl[c][0]);
            split2(S[nA][2], S[nA][3], ph[c][1], pl[c][1]);
            split2(S[nB][0], S[nB][1], ph[c][2], pl[c][2]);
            split2(S[nB][2], S[nB][3], ph[c][3], pl[c][3]);
        }

#pragma unroll
        for (int db = 0; db < 8; db++) {
            D[db][0] *= a0; D[db][1] *= a0;
            D[db][2] *= a1; D[db][3] *= a1;
        }

#pragma unroll
        for (int c = 0; c < 4; c++) {
#pragma unroll
            for (int dbp = 0; dbp < 4; dbp++) {
                uint32_t vh[4], vl[4];
                uint32_t off = (uint32_t)((c * 16 + vb_row) * KPAD + dbp * 16 + vb_col) * 2;
                ldm_x4_t(vh, bVh + off);
                ldm_x4_t(vl, bVl + off);
                mma_bf16(D[2 * dbp],     ph[c], vh);
                mma_bf16(D[2 * dbp],     ph[c], vl);
                mma_bf16(D[2 * dbp],     pl[c], vh);
                mma_bf16(D[2 * dbp + 1], ph[c], vh + 2);
                mma_bf16(D[2 * dbp + 1], ph[c], vl + 2);
                mma_bf16(D[2 * dbp + 1], pl[c], vh + 2);
            }
        }
        __syncthreads();
    }

    float inv0 = 1.0f / lr[0];
    float inv1 = 1.0f / lr[1];
    int row0 = qt * 64 + wid * 16 + g;
#pragma unroll
    for (int db = 0; db < 8; db++) {
        int col = h * HD + db * 8 + 2 * t;
        uint32_t h0, l0, h1, l1;
        split2(D[db][0] * inv0, D[db][1] * inv0, h0, l0);
        split2(D[db][2] * inv1, D[db][3] * inv1, h1, l1);
        *reinterpret_cast<uint32_t*>(g_aoh + (size_t)row0 * DIM + col) = h0;
        *reinterpret_cast<uint32_t*>(g_aol + (size_t)row0 * DIM + col) = l0;
        *reinterpret_cast<uint32_t*>(g_aoh + (size_t)(row0 + 8) * DIM + col) = h1;
        *reinterpret_cast<uint32_t*>(g_aol + (size_t)(row0 + 8) * DIM + col) = l1;
    }
}

// ---------------------------------------------------------------------------
// Launch
// ---------------------------------------------------------------------------
extern "C" void kernel_launch(void* const* d_in, const int* in_sizes, int n_in,
                              void* d_out, int out_size) {
    const float* x  = (const float*)d_in[0];
    const float* wq = (const float*)d_in[1];
    const float* wk = (const float*)d_in[2];
    const float* wv = (const float*)d_in[3];
    const float* wo = (const float*)d_in[4];
    float* out = (float*)d_out;

    static bool configured = false;
    if (!configured) {
        cudaFuncSetAttribute(qkv_gemm,
                             cudaFuncAttributeMaxDynamicSharedMemorySize, GEMM_SMEM);
        cudaFuncSetAttribute(o_gemm,
                             cudaFuncAttributeMaxDynamicSharedMemorySize, GEMM_SMEM);
        cudaFuncSetAttribute(attn_tc_kernel,
                             cudaFuncAttributeMaxDynamicSharedMemorySize, ATTN_SMEM);
        configured = true;
    }

    rope_table_kernel<<<S_LEN, 32>>>();
    conv_split_all<<<(C5 + 255) / 256, 256>>>(
        (const float4*)x, (const float4*)wq, (const float4*)wk,
        (const float4*)wv, (const float4*)wo);
    qkv_gemm<<<dim3(24, 16), 256, GEMM_SMEM>>>();
    attn_tc_kernel<<<dim3(S_LEN / 64, NH), 128, ATTN_SMEM>>>();
    o_gemm<<<dim3(16, 16), 256, GEMM_SMEM>>>(out);
}

// round 14
// speedup vs baseline: 1.1510x; 1.0267x over previous
#include <cuda_runtime.h>
#include <cuda_bf16.h>
#include <math.h>
#include <stdint.h>

#define S_LEN 2048
#define DIM 2048
#define NH 32
#define NKV 8
#define HD 64
#define KVDIM (NKV * HD)   // 512

// ---------------------------------------------------------------------------
// Scratch (bf16 hi/lo pairs stored as uint16)
// ---------------------------------------------------------------------------
__device__ __align__(16) uint16_t g_xh[S_LEN * DIM],  g_xl[S_LEN * DIM];
__device__ __align__(16) uint16_t g_wqh[DIM * DIM],   g_wql[DIM * DIM];
__device__ __align__(16) uint16_t g_wkh[KVDIM * DIM], g_wkl[KVDIM * DIM];
__device__ __align__(16) uint16_t g_wvh[KVDIM * DIM], g_wvl[KVDIM * DIM];
__device__ __align__(16) uint16_t g_woh[DIM * DIM],   g_wol[DIM * DIM];
__device__ __align__(16) uint16_t g_qh[S_LEN * DIM],  g_ql[S_LEN * DIM];
__device__ __align__(16) uint16_t g_kh[S_LEN * KVDIM], g_kl[S_LEN * KVDIM];
__device__ __align__(16) uint16_t g_vh[S_LEN * KVDIM], g_vl[S_LEN * KVDIM];
__device__ __align__(16) uint16_t g_aoh[S_LEN * DIM], g_aol[S_LEN * DIM];
__device__ float g_ct[S_LEN * 32];
__device__ float g_st[S_LEN * 32];

// ---------------------------------------------------------------------------
// helpers
// ---------------------------------------------------------------------------
__device__ __forceinline__ uint32_t smem_u32(const void* p) {
    uint32_t a;
    asm("{ .reg .u64 t; cvta.to.shared.u64 t, %1; cvt.u32.u64 %0, t; }"
        : "=r"(a) : "l"(p));
    return a;
}
__device__ __forceinline__ void ldm_x4(uint32_t* r, uint32_t addr) {
    asm volatile("ldmatrix.sync.aligned.m8n8.x4.shared.b16 {%0,%1,%2,%3}, [%4];"
                 : "=r"(r[0]), "=r"(r[1]), "=r"(r[2]), "=r"(r[3]) : "r"(addr));
}
__device__ __forceinline__ void ldm_x4_t(uint32_t* r, uint32_t addr) {
    asm volatile("ldmatrix.sync.aligned.m8n8.x4.trans.shared.b16 {%0,%1,%2,%3}, [%4];"
                 : "=r"(r[0]), "=r"(r[1]), "=r"(r[2]), "=r"(r[3]) : "r"(addr));
}
__device__ __forceinline__ void mma_bf16(float* d, const uint32_t* a,
                                         const uint32_t* b) {
    asm volatile(
        "mma.sync.aligned.m16n8k16.row.col.f32.bf16.bf16.f32 "
        "{%0,%1,%2,%3}, {%4,%5,%6,%7}, {%8,%9}, {%0,%1,%2,%3};"
        : "+f"(d[0]), "+f"(d[1]), "+f"(d[2]), "+f"(d[3])
        : "r"(a[0]), "r"(a[1]), "r"(a[2]), "r"(a[3]), "r"(b[0]), "r"(b[1]));
}
__device__ __forceinline__ void split2(float x, float y, uint32_t& hi, uint32_t& lo) {
    __nv_bfloat162 h = __float22bfloat162_rn(make_float2(x, y));
    hi = *reinterpret_cast<uint32_t*>(&h);
    __nv_bfloat162 l = __float22bfloat162_rn(make_float2(
        x - __bfloat162float(h.x), y - __bfloat162float(h.y)));
    lo = *reinterpret_cast<uint32_t*>(&l);
}

#define CP_ASYNC16(dst_u32, gsrc) \
    asm volatile("cp.async.cg.shared.global [%0], [%1], 16;" \
                 :: "r"(dst_u32), "l"(gsrc) : "memory")
#define CP_COMMIT() asm volatile("cp.async.commit_group;" ::: "memory")
#define CP_WAIT(n)  asm volatile("cp.async.wait_group %0;" :: "n"(n) : "memory")

// ---------------------------------------------------------------------------
// Fused fp32 -> bf16 hi/lo split for all five inputs (one launch)
// ---------------------------------------------------------------------------
#define N4_X  (S_LEN * DIM / 4)
#define N4_WQ (DIM * DIM / 4)
#define N4_WK (KVDIM * DIM / 4)
#define N4_WV (KVDIM * DIM / 4)
#define N4_WO (DIM * DIM / 4)
#define C1 (N4_X)
#define C2 (C1 + N4_WQ)
#define C3 (C2 + N4_WK)
#define C4 (C3 + N4_WV)
#define C5 (C4 + N4_WO)

__global__ __launch_bounds__(256)
void conv_split_all(const float4* __restrict__ x, const float4* __restrict__ wq,
                    const float4* __restrict__ wk, const float4* __restrict__ wv,
                    const float4* __restrict__ wo) {
    int i = blockIdx.x * 256 + threadIdx.x;
    if (i >= C5) return;
    const float4* src;
    uint2 *dh, *dl;
    int j;
    if (i < C1)      { src = x;  dh = (uint2*)g_xh;  dl = (uint2*)g_xl;  j = i; }
    else if (i < C2) { src = wq; dh = (uint2*)g_wqh; dl = (uint2*)g_wql; j = i - C1; }
    else if (i < C3) { src = wk; dh = (uint2*)g_wkh; dl = (uint2*)g_wkl; j = i - C2; }
    else if (i < C4) { src = wv; dh = (uint2*)g_wvh; dl = (uint2*)g_wvl; j = i - C3; }
    else             { src = wo; dh = (uint2*)g_woh; dl = (uint2*)g_wol; j = i - C4; }
    float4 f = src[j];
    uint2 h, l;
    split2(f.x, f.y, h.x, l.x);
    split2(f.z, f.w, h.y, l.y);
    dh[j] = h;
    dl[j] = l;
}

// ---------------------------------------------------------------------------
// RoPE cos/sin table (verified: fp32 angle, high-precision trig)
// ---------------------------------------------------------------------------
__global__ void rope_table_kernel() {
    int s = blockIdx.x;
    int i = threadIdx.x;
    float e = (float)i / 32.0f;
    float fr = 1.0f / powf(10000.0f, e);
    float angf = (float)s * fr;
    double ang = (double)angf;
    g_ct[s * 32 + i] = (float)cos(ang);
    g_st[s * 32 + i] = (float)sin(ang);
}

// ---------------------------------------------------------------------------
// GEMM core (2-stage cp.async ring, 128 threads / 4 warps, warp tile 64x64)
// ---------------------------------------------------------------------------
#define GPAD 40
#define GSZ (128 * GPAD)
#define GEMM_SMEM (8 * GSZ * 2)   // 81920 bytes

__device__ __forceinline__ void gemm_load_chunk(
    uint32_t sb, int stage, int tid, int m0, int bn0, int k0,
    const uint16_t* Ah, const uint16_t* Al,
    const uint16_t* Bh, const uint16_t* Bl, int K) {
    const uint32_t st = sb + (uint32_t)stage * 4 * GSZ * 2;
#pragma unroll
    for (int i = 0; i < 4; i++) {
        int cid = tid + i * 128;
        int r = cid >> 2;
        int c = (cid & 3) * 8;
        uint32_t soff = (uint32_t)(r * GPAD + c) * 2;
        CP_ASYNC16(st + 0 * GSZ * 2 + soff, Ah + (size_t)(m0 + r) * K + k0 + c);
        CP_ASYNC16(st + 1 * GSZ * 2 + soff, Al + (size_t)(m0 + r) * K + k0 + c);
        CP_ASYNC16(st + 2 * GSZ * 2 + soff, Bh + (size_t)(bn0 + r) * K + k0 + c);
        CP_ASYNC16(st + 3 * GSZ * 2 + soff, Bl + (size_t)(bn0 + r) * K + k0 + c);
    }
}

__device__ __forceinline__ void gemm_compute_chunk(
    uint32_t sb, int stage, float acc[4][8][4],
    int wm, int wn, int a_r, int a_c, int b_r, int b_c) {
    const uint32_t st = sb + (uint32_t)stage * 4 * GSZ * 2;
    const uint32_t bAh = st, bAl = st + GSZ * 2;
    const uint32_t bBh = st + 2 * GSZ * 2, bBl = st + 3 * GSZ * 2;
#pragma unroll
    for (int ks = 0; ks < 2; ks++) {
        const int kc = ks * 16;
        uint32_t ah[4][4], al[4][4];
#pragma unroll
        for (int mi = 0; mi < 4; mi++) {
            uint32_t off = (uint32_t)((wm + mi * 16 + a_r) * GPAD + kc + a_c) * 2;
            ldm_x4(ah[mi], bAh + off);
            ldm_x4(al[mi], bAl + off);
        }
        uint32_t bh[8][2], bl[8][2];
#pragma unroll
        for (int nj = 0; nj < 4; nj++) {
            uint32_t off = (uint32_t)((wn + nj * 16 + b_r) * GPAD + kc + b_c) * 2;
            uint32_t t[4];
            ldm_x4(t, bBh + off);
            bh[nj * 2][0] = t[0]; bh[nj * 2][1] = t[1];
            bh[nj * 2 + 1][0] = t[2]; bh[nj * 2 + 1][1] = t[3];
            ldm_x4(t, bBl + off);
            bl[nj * 2][0] = t[0]; bl[nj * 2][1] = t[1];
            bl[nj * 2 + 1][0] = t[2]; bl[nj * 2 + 1][1] = t[3];
        }
#pragma unroll
        for (int mi = 0; mi < 4; mi++)
#pragma unroll
            for (int ni = 0; ni < 8; ni++) {
                mma_bf16(acc[mi][ni], ah[mi], bh[ni]);
                mma_bf16(acc[mi][ni], ah[mi], bl[ni]);
                mma_bf16(acc[mi][ni], al[mi], bh[ni]);
            }
    }
}

// ---------------------------------------------------------------------------
// Fused QKV GEMM + RoPE/scale/split epilogue. Grid (24, 16), 128 threads.
// Warp layout: wm = (wid&1)*64, wn = (wid>>1)*64.
// ---------------------------------------------------------------------------
__global__ __launch_bounds__(128, 2)
void qkv_gemm() {
    extern __shared__ uint16_t dsm[];
    const uint32_t sb = smem_u32(dsm);

    const int tid  = threadIdx.x;
    const int wid  = tid >> 5;
    const int lane = tid & 31;
    const int wm = (wid & 1) * 64;
    const int wn = (wid >> 1) * 64;
    const int m0 = blockIdx.y * 128;
    const int n0 = blockIdx.x * 128;

    const uint16_t *Bh, *Bl;
    int bn0, seg;
    if (n0 < 2048)      { Bh = g_wqh; Bl = g_wql; bn0 = n0;        seg = 0; }
    else if (n0 < 2560) { Bh = g_wkh; Bl = g_wkl; bn0 = n0 - 2048; seg = 1; }
    else                { Bh = g_wvh; Bl = g_wvl; bn0 = n0 - 2560; seg = 2; }

    float acc[4][8][4];
#pragma unroll
    for (int i = 0; i < 4; i++)
#pragma unroll
        for (int j = 0; j < 8; j++)
#pragma unroll
            for (int e = 0; e < 4; e++) acc[i][j][e] = 0.f;

    const int a_r = lane & 15;
    const int a_c = (lane >> 4) << 3;
    const int b_r = (lane & 7) + ((lane >> 4) << 3);
    const int b_c = ((lane >> 3) & 1) << 3;

    gemm_load_chunk(sb, 0, tid, m0, bn0, 0, g_xh, g_xl, Bh, Bl, DIM);
    CP_COMMIT();

    for (int ck = 0; ck < 64; ck++) {
        const int cur = ck & 1;
        CP_WAIT(0);
        __syncthreads();
        if (ck + 1 < 64) {
            gemm_load_chunk(sb, (ck + 1) & 1, tid, m0, bn0, (ck + 1) * 32,
                            g_xh, g_xl, Bh, Bl, DIM);
            CP_COMMIT();
        }
        gemm_compute_chunk(sb, cur, acc, wm, wn, a_r, a_c, b_r, b_c);
    }

    // ---- epilogue ----
    const int g2 = lane >> 2, t2 = lane & 3;
    if (seg < 2) {
        const int W = (seg == 0) ? DIM : KVDIM;
        uint16_t* dsth = (seg == 0) ? g_qh : g_kh;
        uint16_t* dstl = (seg == 0) ? g_ql : g_kl;
        const float scale = (seg == 0) ? 0.125f : 1.0f;
        const int cb = bn0 + wn;
#pragma unroll
        for (int mi = 0; mi < 4; mi++) {
            int r0 = m0 + wm + mi * 16 + g2;
#pragma unroll
            for (int ni = 0; ni < 4; ni++) {
                int jj = ni * 8 + 2 * t2;
                float2 c0 = *reinterpret_cast<const float2*>(g_ct + r0 * 32 + jj);
                float2 s0 = *reinterpret_cast<const float2*>(g_st + r0 * 32 + jj);
                float2 c1 = *reinterpret_cast<const float2*>(g_ct + (r0 + 8) * 32 + jj);
                float2 s1 = *reinterpret_cast<const float2*>(g_st + (r0 + 8) * 32 + jj);
                uint32_t h, l;
                float x1a = acc[mi][ni][0],     x1b = acc[mi][ni][1];
                float x2a = acc[mi][ni + 4][0], x2b = acc[mi][ni + 4][1];
                split2((x1a * c0.x - x2a * s0.x) * scale,
                       (x1b * c0.y - x2b * s0.y) * scale, h, l);
                *reinterpret_cast<uint32_t*>(dsth + (size_t)r0 * W + cb + jj) = h;
                *reinterpret_cast<uint32_t*>(dstl + (size_t)r0 * W + cb + jj) = l;
                split2((x2a * c0.x + x1a * s0.x) * scale,
                       (x2b * c0.y + x1b * s0.y) * scale, h, l);
                *reinterpret_cast<uint32_t*>(dsth + (size_t)r0 * W + cb + jj + 32) = h;
                *reinterpret_cast<uint32_t*>(dstl + (size_t)r0 * W + cb + jj + 32) = l;
                x1a = acc[mi][ni][2];     x1b = acc[mi][ni][3];
                x2a = acc[mi][ni + 4][2]; x2b = acc[mi][ni + 4][3];
                split2((x1a * c1.x - x2a * s1.x) * scale,
                       (x1b * c1.y - x2b * s1.y) * scale, h, l);
                *reinterpret_cast<uint32_t*>(dsth + (size_t)(r0 + 8) * W + cb + jj) = h;
                *reinterpret_cast<uint32_t*>(dstl + (size_t)(r0 + 8) * W + cb + jj) = l;
                split2((x2a * c1.x + x1a * s1.x) * scale,
                       (x2b * c1.y + x1b * s1.y) * scale, h, l);
                *reinterpret_cast<uint32_t*>(dsth + (size_t)(r0 + 8) * W + cb + jj + 32) = h;
                *reinterpret_cast<uint32_t*>(dstl + (size_t)(r0 + 8) * W + cb + jj + 32) = l;
            }
        }
    } else {
        const int cb = bn0 + wn;
#pragma unroll
        for (int mi = 0; mi < 4; mi++) {
            int r0 = m0 + wm + mi * 16 + g2;
#pragma unroll
            for (int ni = 0; ni < 8; ni++) {
                int cc = cb + ni * 8 + 2 * t2;
                uint32_t h, l;
                split2(acc[mi][ni][0], acc[mi][ni][1], h, l);
                *reinterpret_cast<uint32_t*>(g_vh + (size_t)r0 * KVDIM + cc) = h;
                *reinterpret_cast<uint32_t*>(g_vl + (size_t)r0 * KVDIM + cc) = l;
                split2(acc[mi][ni][2], acc[mi][ni][3], h, l);
                *reinterpret_cast<uint32_t*>(g_vh + (size_t)(r0 + 8) * KVDIM + cc) = h;
                *reinterpret_cast<uint32_t*>(g_vl + (size_t)(r0 + 8) * KVDIM + cc) = l;
            }
        }
    }
}

// ---------------------------------------------------------------------------
// O projection GEMM: out = ao @ wo^T, fp32 output. 128 threads, 4 warps.
// ---------------------------------------------------------------------------
__global__ __launch_bounds__(128, 2)
void o_gemm(float* __restrict__ C) {
    extern __shared__ uint16_t dsm[];
    const uint32_t sb = smem_u32(dsm);

    const int tid  = threadIdx.x;
    const int wid  = tid >> 5;
    const int lane = tid & 31;
    const int wm = (wid & 1) * 64;
    const int wn = (wid >> 1) * 64;
    const int m0 = blockIdx.y * 128;
    const int n0 = blockIdx.x * 128;

    float acc[4][8][4];
#pragma unroll
    for (int i = 0; i < 4; i++)
#pragma unroll
        for (int j = 0; j < 8; j++)
#pragma unroll
            for (int e = 0; e < 4; e++) acc[i][j][e] = 0.f;

    const int a_r = lane & 15;
    const int a_c = (lane >> 4) << 3;
    const int b_r = (lane & 7) + ((lane >> 4) << 3);
    const int b_c = ((lane >> 3) & 1) << 3;

    gemm_load_chunk(sb, 0, tid, m0, n0, 0, g_aoh, g_aol, g_woh, g_wol, DIM);
    CP_COMMIT();

    for (int ck = 0; ck < 64; ck++) {
        const int cur = ck & 1;
        CP_WAIT(0);
        __syncthreads();
        if (ck + 1 < 64) {
            gemm_load_chunk(sb, (ck + 1) & 1, tid, m0, n0, (ck + 1) * 32,
                            g_aoh, g_aol, g_woh, g_wol, DIM);
            CP_COMMIT();
        }
        gemm_compute_chunk(sb, cur, acc, wm, wn, a_r, a_c, b_r, b_c);
    }

    const int g2 = lane >> 2, t2 = lane & 3;
#pragma unroll
    for (int mi = 0; mi < 4; mi++) {
        int r0 = m0 + wm + mi * 16 + g2;
#pragma unroll
        for (int ni = 0; ni < 8; ni++) {
            int c = n0 + wn + ni * 8 + t2 * 2;
            *reinterpret_cast<float2*>(C + (size_t)r0 * DIM + c) =
                make_float2(acc[mi][ni][0], acc[mi][ni][1]);
            *reinterpret_cast<float2*>(C + (size_t)(r0 + 8) * DIM + c) =
                make_float2(acc[mi][ni][2], acc[mi][ni][3]);
        }
    }
}

// ---------------------------------------------------------------------------
// Tensor-core flash attention (unchanged from R13 — measured best)
// ---------------------------------------------------------------------------
#define KPAD 72
#define AARR (64 * KPAD * 2)
#define ASTG (4 * AARR)
#define ATTN_SMEM (2 * ASTG)      // 73728
#define LOG2E 1.4426950408889634f

__global__ __launch_bounds__(128, 3)
void attn_tc_kernel() {
    extern __shared__ uint16_t asm_[];
    const uint32_t sb = smem_u32(asm_);

    const int qt = (int)gridDim.x - 1 - (int)blockIdx.x;
    const int h  = blockIdx.y;
    const int kvh = h >> 2;
    const int tid = threadIdx.x;
    const int wid = tid >> 5;
    const int lane = tid & 31;
    const int g = lane >> 2;
    const int t = lane & 3;

#pragma unroll
    for (int it = 0; it < 4; it++) {
        int cid = tid + it * 128;
        int r = cid >> 3;
        int c = (cid & 7) * 8;
        *reinterpret_cast<uint4*>(&asm_[(0 * AARR / 2) + r * KPAD + c]) =
            *reinterpret_cast<const uint4*>(
                g_qh + (size_t)(qt * 64 + r) * DIM + h * HD + c);
        *reinterpret_cast<uint4*>(&asm_[(1 * AARR / 2) + r * KPAD + c]) =
            *reinterpret_cast<const uint4*>(
                g_ql + (size_t)(qt * 64 + r) * DIM + h * HD + c);
    }
    __syncthreads();

    uint32_t qh[4][4], ql[4][4];
    {
        int row = wid * 16 + (lane & 15);
        int col = ((lane >> 4) & 1) * 8;
#pragma unroll
        for (int c = 0; c < 4; c++) {
            uint32_t off = (uint32_t)(row * KPAD + c * 16 + col) * 2;
            ldm_x4(qh[c], sb + 0 * AARR + off);
            ldm_x4(ql[c], sb + 1 * AARR + off);
        }
    }
    __syncthreads();

    float mr[2] = {-INFINITY, -INFINITY};
    float lr[2] = {0.f, 0.f};
    float D[8][4];
#pragma unroll
    for (int i = 0; i < 8; i++)
#pragma unroll
        for (int j = 0; j < 4; j++) D[i][j] = 0.f;

    const int kb_row = (lane & 7) + ((lane >> 4) << 3);
    const int kb_col = ((lane >> 3) & 1) * 8;
    const int vb_row = (lane & 7) + (((lane >> 3) & 1) << 3);
    const int vb_col = ((lane >> 4) & 1) * 8;

    auto stage_kv = [&](int kt, int stage) {
        const uint32_t st = sb + (uint32_t)stage * ASTG;
#pragma unroll
        for (int it = 0; it < 4; it++) {
            int cid = tid + it * 128;
            int r = cid >> 3;
            int c = (cid & 7) * 8;
            size_t off = (size_t)(kt * 64 + r) * KVDIM + kvh * HD + c;
            uint32_t soff = (uint32_t)(r * KPAD + c) * 2;
            CP_ASYNC16(st + 0 * AARR + soff, g_kh + off);
            CP_ASYNC16(st + 1 * AARR + soff, g_kl + off);
            CP_ASYNC16(st + 2 * AARR + soff, g_vh + off);
            CP_ASYNC16(st + 3 * AARR + soff, g_vl + off);
        }
    };

    stage_kv(0, 0);
    CP_COMMIT();

    for (int kt = 0; kt <= qt; kt++) {
        const uint32_t st = sb + (uint32_t)(kt & 1) * ASTG;
        const uint32_t bKh = st, bKl = st + AARR;
        const uint32_t bVh = st + 2 * AARR, bVl = st + 3 * AARR;

        CP_WAIT(0);
        __syncthreads();
        if (kt < qt) {
            stage_kv(kt + 1, (kt + 1) & 1);
            CP_COMMIT();
        }

        float S[8][4];
#pragma unroll
        for (int i = 0; i < 8; i++)
#pragma unroll
            for (int j = 0; j < 4; j++) S[i][j] = 0.f;

#pragma unroll
        for (int c = 0; c < 4; c++) {
#pragma unroll
            for (int nbp = 0; nbp < 4; nbp++) {
                uint32_t kh[4], kl[4];
                uint32_t off = (uint32_t)((nbp * 16 + kb_row) * KPAD + c * 16 + kb_col) * 2;
                ldm_x4(kh, bKh + off);
                ldm_x4(kl, bKl + off);
                mma_bf16(S[2 * nbp],     qh[c], kh);
                mma_bf16(S[2 * nbp],     qh[c], kl);
                mma_bf16(S[2 * nbp],     ql[c], kh);
                mma_bf16(S[2 * nbp + 1], qh[c], kh + 2);
                mma_bf16(S[2 * nbp + 1], qh[c], kl + 2);
                mma_bf16(S[2 * nbp + 1], ql[c], kh + 2);
            }
        }

        if (kt == qt) {
            int r0 = wid * 16 + g;
#pragma unroll
            for (int nb = 0; nb < 8; nb++) {
                int c0 = nb * 8 + 2 * t;
                if (c0 > r0)     S[nb][0] = -INFINITY;
                if (c0 + 1 > r0) S[nb][1] = -INFINITY;
                if (c0 > r0 + 8)     S[nb][2] = -INFINITY;
                if (c0 + 1 > r0 + 8) S[nb][3] = -INFINITY;
            }
        }

        float mx0 = -INFINITY, mx1 = -INFINITY;
#pragma unroll
        for (int nb = 0; nb < 8; nb++) {
            mx0 = fmaxf(mx0, fmaxf(S[nb][0], S[nb][1]));
            mx1 = fmaxf(mx1, fmaxf(S[nb][2], S[nb][3]));
        }
        mx0 = fmaxf(mx0, __shfl_xor_sync(0xffffffffu, mx0, 1));
        mx0 = fmaxf(mx0, __shfl_xor_sync(0xffffffffu, mx0, 2));
        mx1 = fmaxf(mx1, __shfl_xor_sync(0xffffffffu, mx1, 1));
        mx1 = fmaxf(mx1, __shfl_xor_sync(0xffffffffu, mx1, 2));
        float newm0 = fmaxf(mr[0], mx0);
        float newm1 = fmaxf(mr[1], mx1);
        float a0 = exp2f((mr[0] - newm0) * LOG2E);
        float a1 = exp2f((mr[1] - newm1) * LOG2E);
        mr[0] = newm0; mr[1] = newm1;

        float sum0 = 0.f, sum1 = 0.f;
#pragma unroll
        for (int nb = 0; nb < 8; nb++) {
            S[nb][0] = exp2f((S[nb][0] - newm0) * LOG2E);
            S[nb][1] = exp2f((S[nb][1] - newm0) * LOG2E);
            S[nb][2] = exp2f((S[nb][2] - newm1) * LOG2E);
            S[nb][3] = exp2f((S[nb][3] - newm1) * LOG2E);
            sum0 += S[nb][0] + S[nb][1];
            sum1 += S[nb][2] + S[nb][3];
        }
        sum0 += __shfl_xor_sync(0xffffffffu, sum0, 1);
        sum0 += __shfl_xor_sync(0xffffffffu, sum0, 2);
        sum1 += __shfl_xor_sync(0xffffffffu, sum1, 1);
        sum1 += __shfl_xor_sync(0xffffffffu, sum1, 2);
        lr[0] = lr[0] * a0 + sum0;
        lr[1] = lr[1] * a1 + sum1;

        uint32_t ph[4][4], pl[4][4];
#pragma unroll
        for (int c = 0; c < 4; c++) {
            int nA = 2 * c, nB = 2 * c + 1;
            split2(S[nA][0], S[nA][1], ph[c][0], pl[c][0]);
            split2(S[nA][2], S[nA][3], ph[c][1], pl[c][1]);
            split2(S[nB][0], S[nB][1], ph[c][2], pl[c][2]);
            split2(S[nB][2], S[nB][3], ph[c][3], pl[c][3]);
        }

#pragma unroll
        for (int db = 0; db < 8; db++) {
            D[db][0] *= a0; D[db][1] *= a0;
            D[db][2] *= a1; D[db][3] *= a1;
        }

#pragma unroll
        for (int c = 0; c < 4; c++) {
#pragma unroll
            for (int dbp = 0; dbp < 4; dbp++) {
                uint32_t vh[4], vl[4];
                uint32_t off = (uint32_t)((c * 16 + vb_row) * KPAD + dbp * 16 + vb_col) * 2;
                ldm_x4_t(vh, bVh + off);
                ldm_x4_t(vl, bVl + off);
                mma_bf16(D[2 * dbp],     ph[c], vh);
                mma_bf16(D[2 * dbp],     ph[c], vl);
                mma_bf16(D[2 * dbp],     pl[c], vh);
                mma_bf16(D[2 * dbp + 1], ph[c], vh + 2);
                mma_bf16(D[2 * dbp + 1], ph[c], vl + 2);
                mma_bf16(D[2 * dbp + 1], pl[c], vh + 2);
            }
        }
        __syncthreads();
    }

    float inv0 = 1.0f / lr[0];
    float inv1 = 1.0f / lr[1];
    int row0 = qt * 64 + wid * 16 + g;
#pragma unroll
    for (int db = 0; db < 8; db++) {
        int col = h * HD + db * 8 + 2 * t;
        uint32_t h0, l0, h1, l1;
        split2(D[db][0] * inv0, D[db][1] * inv0, h0, l0);
        split2(D[db][2] * inv1, D[db][3] * inv1, h1, l1);
        *reinterpret_cast<uint32_t*>(g_aoh + (size_t)row0 * DIM + col) = h0;
        *reinterpret_cast<uint32_t*>(g_aol + (size_t)row0 * DIM + col) = l0;
        *reinterpret_cast<uint32_t*>(g_aoh + (size_t)(row0 + 8) * DIM + col) = h1;
        *reinterpret_cast<uint32_t*>(g_aol + (size_t)(row0 + 8) * DIM + col) = l1;
    }
}

// ---------------------------------------------------------------------------
// Launch
// ---------------------------------------------------------------------------
extern "C" void kernel_launch(void* const* d_in, const int* in_sizes, int n_in,
                              void* d_out, int out_size) {
    const float* x  = (const float*)d_in[0];
    const float* wq = (const float*)d_in[1];
    const float* wk = (const float*)d_in[2];
    const float* wv = (const float*)d_in[3];
    const float* wo = (const float*)d_in[4];
    float* out = (float*)d_out;

    static bool configured = false;
    if (!configured) {
        cudaFuncSetAttribute(qkv_gemm,
                             cudaFuncAttributeMaxDynamicSharedMemorySize, GEMM_SMEM);
        cudaFuncSetAttribute(o_gemm,
                             cudaFuncAttributeMaxDynamicSharedMemorySize, GEMM_SMEM);
        cudaFuncSetAttribute(attn_tc_kernel,
                             cudaFuncAttributeMaxDynamicSharedMemorySize, ATTN_SMEM);
        configured = true;
    }

    rope_table_kernel<<<S_LEN, 32>>>();
    conv_split_all<<<(C5 + 255) / 256, 256>>>(
        (const float4*)x, (const float4*)wq, (const float4*)wk,
        (const float4*)wv, (const float4*)wo);
    qkv_gemm<<<dim3(24, 16), 128, GEMM_SMEM>>>();
    attn_tc_kernel<<<dim3(S_LEN / 64, NH), 128, ATTN_SMEM>>>();
    o_gemm<<<dim3(16, 16), 128, GEMM_SMEM>>>(out);
}